// round 13
// baseline (speedup 1.0000x reference)
#include <cuda_runtime.h>
#include <cuda_bf16.h>
#include <math.h>
#include <stdint.h>

// ---------------- problem constants (all static) ----------------
constexpr int B_    = 8;
constexpr int H0    = 56;
constexpr int W0    = 56;
constexpr int N0    = H0 * W0;        // 3136
constexpr int DIM   = 256;
constexpr int HEADS = 8;
constexpr int HD    = 32;
constexpr int LOCAL = 9;
constexpr int PW    = 7;
constexpr int PLEN  = 49;
constexpr int LTAB  = 4096;
constexpr int MROWS = B_ * N0;        // 25088

// ---------------- scratch (device globals; no allocs) ----------------
__device__ float g_qs[B_*HEADS*N0*HD];
__device__ float g_qn[B_*HEADS*N0*HD];
__device__ float g_k [B_*HEADS*N0*HD];
__device__ float g_v [B_*HEADS*N0*HD];
__device__ float g_xs[B_*N0*DIM];
__device__ float g_kp[B_*HEADS*PLEN*HD];
__device__ float g_vp[B_*HEADS*PLEN*HD];
__device__ float g_tab[LTAB*HEADS];
__device__ float g_pb[HEADS*N0*52];      // precomputed pool_bias [h][n][m]

// packed bf16 hi/lo operands (u32 = 2 bf16 along k)
__device__ uint32_t g_xH [MROWS*128];
__device__ uint32_t g_xL [MROWS*128];
__device__ uint32_t g_xoH[MROWS*128];
__device__ uint32_t g_xoL[MROWS*128];
__device__ uint32_t g_wH [1280*128];     // fused W [col][k2]: q|k|v|sr|proj
__device__ uint32_t g_wL [1280*128];

// ---------------- helpers ----------------
__device__ __forceinline__ uint32_t pack_bf2(__nv_bfloat16 x, __nv_bfloat16 y) {
    __nv_bfloat162 t; t.x = x; t.y = y;
    return *reinterpret_cast<uint32_t*>(&t);
}
__device__ __forceinline__ void split2(float x, float y, uint32_t& hi, uint32_t& lo) {
    __nv_bfloat16 xh = __float2bfloat16_rn(x);
    __nv_bfloat16 yh = __float2bfloat16_rn(y);
    float xr = x - __bfloat162float(xh);
    float yr = y - __bfloat162float(yh);
    hi = pack_bf2(xh, yh);
    lo = pack_bf2(__float2bfloat16_rn(xr), __float2bfloat16_rn(yr));
}

#define MMA16816(d, a0,a1,a2,a3, b0,b1) \
    asm volatile("mma.sync.aligned.m16n8k16.row.col.f32.bf16.bf16.f32 " \
        "{%0,%1,%2,%3},{%4,%5,%6,%7},{%8,%9},{%0,%1,%2,%3};" \
        : "+f"(d[0]), "+f"(d[1]), "+f"(d[2]), "+f"(d[3]) \
        : "r"(a0), "r"(a1), "r"(a2), "r"(a3), "r"(b0), "r"(b1))

#define LDSM4(r, addr) \
    asm volatile("ldmatrix.sync.aligned.m8n8.x4.shared.b16 {%0,%1,%2,%3}, [%4];" \
        : "=r"((r)[0]), "=r"((r)[1]), "=r"((r)[2]), "=r"((r)[3]) : "r"(addr))

__device__ __forceinline__ void cp16(uint32_t dst, const void* src) {
    asm volatile("cp.async.cg.shared.global [%0], [%1], 16;" :: "r"(dst), "l"(src));
}

#define DOT4(acc, a, b) (acc) += (a).x*(b).x + (a).y*(b).y + (a).z*(b).z + (a).w*(b).w

// ---------------- fused pre-kernel: convert x, convert W, cpb MLP ----------------
constexpr int NBLK_CX = MROWS * DIM / 4 / 256;   // 6272
constexpr int NBLK_CW = 1280 * 128 / 256;        // 640
constexpr int NBLK_CPB = LTAB / 8;               // 512

__global__ __launch_bounds__(256)
void pre_kernel(const float* __restrict__ x,
                const float* __restrict__ q_w, const float* __restrict__ kv_w,
                const float* __restrict__ sr_w, const float* __restrict__ proj_w,
                const float* __restrict__ rct,
                const float* __restrict__ w1, const float* __restrict__ b1,
                const float* __restrict__ w2, const float* __restrict__ b2)
{
    int blk = blockIdx.x, tid = threadIdx.x;
    if (blk < NBLK_CX) {
        int i = blk * 256 + tid;
        float4 v = reinterpret_cast<const float4*>(x)[i];
        uint32_t h0, l0, h1, l1;
        split2(v.x, v.y, h0, l0);
        split2(v.z, v.w, h1, l1);
        g_xH[i * 2] = h0; g_xH[i * 2 + 1] = h1;
        g_xL[i * 2] = l0; g_xL[i * 2 + 1] = l1;
    } else if (blk < NBLK_CX + NBLK_CW) {
        int idx = (blk - NBLK_CX) * 256 + tid;
        int c = idx >> 7, k2 = idx & 127;
        float f0, f1;
        if (c < 256)       { f0 = q_w [(2*k2)   * 256 + c];        f1 = q_w [(2*k2+1) * 256 + c];        }
        else if (c < 768)  { f0 = kv_w[(2*k2)   * 512 + c - 256];  f1 = kv_w[(2*k2+1) * 512 + c - 256];  }
        else if (c < 1024) { f0 = sr_w[(2*k2)   * 256 + c - 768];  f1 = sr_w[(2*k2+1) * 256 + c - 768];  }
        else               { f0 = proj_w[(2*k2) * 256 + c - 1024]; f1 = proj_w[(2*k2+1) * 256 + c - 1024]; }
        uint32_t h, l;
        split2(f0, f1, h, l);
        g_wH[idx] = h; g_wL[idx] = l;
    } else {
        int gw = ((blk - NBLK_CX - NBLK_CW) * 256 + tid) >> 5;
        int lane = tid & 31;
        float r0 = rct[gw * 2], r1 = rct[gw * 2 + 1];
        float acc[HEADS];
#pragma unroll
        for (int h = 0; h < HEADS; h++) acc[h] = 0.f;
        for (int j = lane; j < 512; j += 32) {
            float hv = fmaxf(r0 * w1[j] + r1 * w1[512 + j] + b1[j], 0.f);
#pragma unroll
            for (int h = 0; h < HEADS; h++) acc[h] += hv * w2[j * HEADS + h];
        }
#pragma unroll
        for (int h = 0; h < HEADS; h++)
#pragma unroll
            for (int o = 16; o; o >>= 1) acc[h] += __shfl_xor_sync(0xffffffffu, acc[h], o);
        if (lane == 0) {
#pragma unroll
            for (int h = 0; h < HEADS; h++) g_tab[gw * HEADS + h] = acc[h] + b2[h];
        }
    }
}

// ---------------- bf16x3 HMMA GEMM, 128x64 tile, k-chunks of 64, 2-stage ----------------
constexpr int LDU = 36;                       // u32 row stride (32 data + 4 pad)
constexpr uint32_t SM_AL = 18432;             // 128*36*4
constexpr uint32_t SM_BH = 36864;
constexpr uint32_t SM_BL = 46080;             // + 64*36*4
constexpr uint32_t SM_STAGE = 55296;
constexpr int GEMM_SMEM = 110592;             // 2 stages

template<int MODE>
__global__ __launch_bounds__(256, 2)
void gemm_mma_kernel(const float* __restrict__ bq, const float* __restrict__ bkv,
                     const float* __restrict__ bsr,
                     const float* __restrict__ qe, const float* __restrict__ temp,
                     const float* __restrict__ sls,
                     float* __restrict__ Out)
{
    extern __shared__ uint32_t sm_u[];
    uint32_t sbase = (uint32_t)__cvta_generic_to_shared(sm_u);

    const uint32_t* AH = MODE ? g_xoH : g_xH;
    const uint32_t* AL = MODE ? g_xoL : g_xL;

    int tid  = threadIdx.x;
    int lane = tid & 31;
    int warp = tid >> 5;
    int wm   = warp >> 1;
    int wn   = warp & 1;

    int m0    = blockIdx.x * 128;
    int col0  = blockIdx.y * 64;
    int bcol0 = col0 + (MODE ? 1024 : 0);

    // loader mapping: A 128 rows x 32 u32 per chunk; B 64 rows x 32 u32
    int lrowA = tid >> 1;
    int lcolA = (tid & 1) * 16;               // u32
    uint32_t dstA = (uint32_t)(lrowA * LDU + lcolA) * 4;
    int lrowB = tid >> 2;
    int lcolB = (tid & 3) * 8;                // u32
    uint32_t dstB = (uint32_t)(lrowB * LDU + lcolB) * 4;

    const uint32_t* aHp = &AH  [(size_t)(m0 + lrowA)    * 128 + lcolA];
    const uint32_t* aLp = &AL  [(size_t)(m0 + lrowA)    * 128 + lcolA];
    const uint32_t* bHp = &g_wH[(size_t)(bcol0 + lrowB) * 128 + lcolB];
    const uint32_t* bLp = &g_wL[(size_t)(bcol0 + lrowB) * 128 + lcolB];

    int aRow  = wm * 32 + (lane & 7) + ((lane >> 3) & 1) * 8;
    int aCol4 = ((lane >> 4) & 1) * 4;
    uint32_t aoff[2][4];
#pragma unroll
    for (int mt = 0; mt < 2; mt++)
#pragma unroll
        for (int s = 0; s < 4; s++)
            aoff[mt][s] = (uint32_t)(((aRow + mt * 16) * LDU) + s * 8 + aCol4) * 4;
    int bRow  = wn * 32 + (lane & 7);
    int bCol4 = ((lane >> 3) & 3) * 4;
    uint32_t boff[4][2];
#pragma unroll
    for (int nt = 0; nt < 4; nt++)
#pragma unroll
        for (int sb = 0; sb < 2; sb++)
            boff[nt][sb] = (uint32_t)(((bRow + nt * 8) * LDU) + sb * 16 + bCol4) * 4;

    float acc[2][4][4];
#pragma unroll
    for (int i = 0; i < 2; i++)
#pragma unroll
        for (int j = 0; j < 4; j++)
#pragma unroll
            for (int e = 0; e < 4; e++) acc[i][j][e] = 0.f;

#define ISSUE_STAGE(it, buf) do { \
    uint32_t st_ = sbase + (uint32_t)(buf) * SM_STAGE; \
    const uint32_t* aH_ = aHp + (it) * 32; \
    const uint32_t* aL_ = aLp + (it) * 32; \
    cp16(st_ + dstA,               aH_); \
    cp16(st_ + dstA + 16,          aH_ + 4); \
    cp16(st_ + dstA + 32,          aH_ + 8); \
    cp16(st_ + dstA + 48,          aH_ + 12); \
    cp16(st_ + SM_AL + dstA,       aL_); \
    cp16(st_ + SM_AL + dstA + 16,  aL_ + 4); \
    cp16(st_ + SM_AL + dstA + 32,  aL_ + 8); \
    cp16(st_ + SM_AL + dstA + 48,  aL_ + 12); \
    cp16(st_ + SM_BH + dstB,       bHp + (it) * 32); \
    cp16(st_ + SM_BH + dstB + 16,  bHp + (it) * 32 + 4); \
    cp16(st_ + SM_BL + dstB,       bLp + (it) * 32); \
    cp16(st_ + SM_BL + dstB + 16,  bLp + (it) * 32 + 4); \
    asm volatile("cp.async.commit_group;"); \
} while (0)

    ISSUE_STAGE(0, 0);
    ISSUE_STAGE(1, 1);

#pragma unroll
    for (int it = 0; it < 4; it++) {
        if (it < 3) {
            asm volatile("cp.async.wait_group 1;");
        } else {
            asm volatile("cp.async.wait_group 0;");
        }
        __syncthreads();
        {
            uint32_t st = sbase + (uint32_t)(it & 1) * SM_STAGE;
            uint32_t bHf[4][8], bLf[4][8];
#pragma unroll
            for (int nt = 0; nt < 4; nt++) {
#pragma unroll
                for (int sb = 0; sb < 2; sb++) {
                    LDSM4(bHf[nt] + sb * 4, st + SM_BH + boff[nt][sb]);
                    LDSM4(bLf[nt] + sb * 4, st + SM_BL + boff[nt][sb]);
                }
            }
#pragma unroll
            for (int s = 0; s < 4; s++) {
                int bi = (s >> 1) * 4 + (s & 1) * 2;
                uint32_t aHf[2][4], aLf[2][4];
#pragma unroll
                for (int mt = 0; mt < 2; mt++) {
                    LDSM4(aHf[mt], st + aoff[mt][s]);
                    LDSM4(aLf[mt], st + SM_AL + aoff[mt][s]);
                }
#pragma unroll
                for (int mt = 0; mt < 2; mt++)
#pragma unroll
                    for (int nt = 0; nt < 4; nt++) {
                        MMA16816(acc[mt][nt], aHf[mt][0], aHf[mt][1], aHf[mt][2], aHf[mt][3],
                                 bHf[nt][bi], bHf[nt][bi + 1]);
                        MMA16816(acc[mt][nt], aHf[mt][0], aHf[mt][1], aHf[mt][2], aHf[mt][3],
                                 bLf[nt][bi], bLf[nt][bi + 1]);
                        MMA16816(acc[mt][nt], aLf[mt][0], aLf[mt][1], aLf[mt][2], aLf[mt][3],
                                 bHf[nt][bi], bHf[nt][bi + 1]);
                    }
            }
        }
        if (it < 2) {
            __syncthreads();
            ISSUE_STAGE(it + 2, it & 1);
        }
    }
#undef ISSUE_STAGE

    // ---------------- epilogue ----------------
    if (MODE == 1) {
#pragma unroll
        for (int mt = 0; mt < 2; mt++) {
            int r0 = m0 + wm * 32 + mt * 16 + (lane >> 2);
#pragma unroll
            for (int nt = 0; nt < 4; nt++) {
                int c0 = col0 + wn * 32 + nt * 8 + (lane & 3) * 2;
                Out[(size_t)r0 * DIM + c0]           = acc[mt][nt][0] + bq[c0];
                Out[(size_t)r0 * DIM + c0 + 1]       = acc[mt][nt][1] + bq[c0 + 1];
                Out[(size_t)(r0 + 8) * DIM + c0]     = acc[mt][nt][2] + bq[c0];
                Out[(size_t)(r0 + 8) * DIM + c0 + 1] = acc[mt][nt][3] + bq[c0 + 1];
            }
        }
        return;
    }

    int strip = (col0 + wn * 32) >> 5;
#pragma unroll
    for (int mt = 0; mt < 2; mt++)
#pragma unroll
        for (int nt = 0; nt < 4; nt++) {
            int c = col0 + wn * 32 + nt * 8 + (lane & 3) * 2;
            float b0, b1;
            if (c < 256)      { b0 = bq[c];        b1 = bq[c + 1];    }
            else if (c < 768) { b0 = bkv[c - 256]; b1 = bkv[c - 255]; }
            else              { b0 = bsr[c - 768]; b1 = bsr[c - 767]; }
            acc[mt][nt][0] += b0; acc[mt][nt][1] += b1;
            acc[mt][nt][2] += b0; acc[mt][nt][3] += b1;
        }

    if (strip < 16) {
        int h = strip & 7;
        bool isq = strip < 8;
        float spsls = 0.f;
        if (isq) spsls = log1pf(expf(temp[h])) * sls[0];
#pragma unroll
        for (int mt = 0; mt < 2; mt++) {
            float ss0 = 0.f, ss1 = 0.f;
#pragma unroll
            for (int nt = 0; nt < 4; nt++) {
                ss0 += acc[mt][nt][0] * acc[mt][nt][0] + acc[mt][nt][1] * acc[mt][nt][1];
                ss1 += acc[mt][nt][2] * acc[mt][nt][2] + acc[mt][nt][3] * acc[mt][nt][3];
            }
            ss0 += __shfl_xor_sync(0xffffffffu, ss0, 1);
            ss0 += __shfl_xor_sync(0xffffffffu, ss0, 2);
            ss1 += __shfl_xor_sync(0xffffffffu, ss1, 1);
            ss1 += __shfl_xor_sync(0xffffffffu, ss1, 2);
            float inv0 = 1.f / fmaxf(sqrtf(ss0), 1e-12f);
            float inv1 = 1.f / fmaxf(sqrtf(ss1), 1e-12f);
            int r0 = m0 + wm * 32 + mt * 16 + (lane >> 2);
            int b0i = r0 / N0, n0i = r0 % N0;
            int b1i = (r0 + 8) / N0, n1i = (r0 + 8) % N0;
            size_t base0 = (((size_t)(b0i * HEADS + h)) * N0 + n0i) * HD;
            size_t base1 = (((size_t)(b1i * HEADS + h)) * N0 + n1i) * HD;
#pragma unroll
            for (int nt = 0; nt < 4; nt++) {
                int d0 = (wn * 32 + nt * 8 + (lane & 3) * 2) & 31;
#pragma unroll
                for (int p = 0; p < 2; p++) {
                    int d = d0 + p;
                    float v0 = acc[mt][nt][p]     * inv0;
                    float v1 = acc[mt][nt][2 + p] * inv1;
                    if (isq) {
                        float e = qe[h * HD + d];
                        g_qn[base0 + d] = v0;
                        g_qn[base1 + d] = v1;
                        g_qs[base0 + d] = (v0 + e) * spsls;
                        g_qs[base1 + d] = (v1 + e) * spsls;
                    } else {
                        g_k[base0 + d] = v0;
                        g_k[base1 + d] = v1;
                    }
                }
            }
        }
    } else if (strip < 24) {
        int h = strip & 7;
#pragma unroll
        for (int mt = 0; mt < 2; mt++) {
            int r0 = m0 + wm * 32 + mt * 16 + (lane >> 2);
            int ba = r0 / N0, na = r0 % N0;
            int bb = (r0 + 8) / N0, nb = (r0 + 8) % N0;
            size_t base0 = (((size_t)(ba * HEADS + h)) * N0 + na) * HD;
            size_t base1 = (((size_t)(bb * HEADS + h)) * N0 + nb) * HD;
#pragma unroll
            for (int nt = 0; nt < 4; nt++) {
                int d = (wn * 32 + nt * 8 + (lane & 3) * 2) & 31;
                g_v[base0 + d]     = acc[mt][nt][0];
                g_v[base0 + d + 1] = acc[mt][nt][1];
                g_v[base1 + d]     = acc[mt][nt][2];
                g_v[base1 + d + 1] = acc[mt][nt][3];
            }
        }
    } else {
#pragma unroll
        for (int mt = 0; mt < 2; mt++) {
            int r0 = m0 + wm * 32 + mt * 16 + (lane >> 2);
            int ba = r0 / N0, na = r0 % N0;
            int bb = (r0 + 8) / N0, nb = (r0 + 8) % N0;
#pragma unroll
            for (int nt = 0; nt < 4; nt++) {
                int cc = (wn * 32 + nt * 8 + (lane & 3) * 2) + col0 - 768;
#pragma unroll
                for (int p = 0; p < 2; p++) {
                    float v0 = acc[mt][nt][p];
                    float v1 = acc[mt][nt][2 + p];
                    g_xs[((size_t)(ba * N0 + na)) * DIM + cc + p] =
                        0.5f * v0 * (1.f + erff(v0 * 0.70710678118654752f));
                    g_xs[((size_t)(bb * N0 + nb)) * DIM + cc + p] =
                        0.5f * v1 * (1.f + erff(v1 * 0.70710678118654752f));
                }
            }
        }
    }
}

// ---------------- fused mid-kernel: pool+LN+kvp and pool_bias precompute ----------------
constexpr int NBLK_PK = B_ * PLEN / 4 * 2;           // 196
constexpr int NBLK_PB = (HEADS * N0 * PLEN + 255) / 256; // 4803

__global__ __launch_bounds__(256)
void mid_kernel(const float* __restrict__ gamma, const float* __restrict__ beta,
                const float* __restrict__ kv_w, const float* __restrict__ kv_b,
                const int* __restrict__ rpi)
{
    int blk = blockIdx.x, tid = threadIdx.x;
    if (blk >= NBLK_PK) {
        int idx = (blk - NBLK_PK) * 256 + tid;
        if (idx < HEADS * N0 * PLEN) {
            int m = idx % PLEN;
            int hn = idx / PLEN;
            g_pb[(size_t)hn * 52 + m] = g_tab[rpi[(hn % N0) * PLEN + m] * HEADS + (hn / N0)];
        }
        return;
    }

    __shared__ float xr[4][DIM];
    __shared__ float redm[4][8], redv[4][8];
    int bp0 = (blk >> 1) * 4;
    int half = blk & 1;
    int lane = tid & 31, wp = tid >> 5;

    float sv[4];
#pragma unroll
    for (int i = 0; i < 4; i++) {
        int bp = bp0 + i, b = bp / PLEN, p = bp % PLEN;
        int pi = p / PW, pj = p % PW;
        float s = 0.f;
#pragma unroll
        for (int r = 0; r < 8; r++)
#pragma unroll
            for (int c = 0; c < 8; c++)
                s += g_xs[((size_t)(b * N0 + (pi * 8 + r) * W0 + pj * 8 + c)) * DIM + tid];
        sv[i] = s * (1.f / 64.f);
    }
#pragma unroll
    for (int i = 0; i < 4; i++) {
        float m = sv[i];
#pragma unroll
        for (int o = 16; o; o >>= 1) m += __shfl_xor_sync(0xffffffffu, m, o);
        if (lane == 0) redm[i][wp] = m;
    }
    __syncthreads();
    float dv[4];
#pragma unroll
    for (int i = 0; i < 4; i++) {
        float mean = 0.f;
#pragma unroll
        for (int w = 0; w < 8; w++) mean += redm[i][w];
        mean *= (1.f / 256.f);
        dv[i] = sv[i] - mean;
        float v2 = dv[i] * dv[i];
#pragma unroll
        for (int o = 16; o; o >>= 1) v2 += __shfl_xor_sync(0xffffffffu, v2, o);
        if (lane == 0) redv[i][wp] = v2;
    }
    __syncthreads();
#pragma unroll
    for (int i = 0; i < 4; i++) {
        float var = 0.f;
#pragma unroll
        for (int w = 0; w < 8; w++) var += redv[i][w];
        var *= (1.f / 256.f);
        xr[i][tid] = dv[i] * rsqrtf(var + 1e-5f) * gamma[tid] + beta[tid];
    }
    __syncthreads();

    int yoff = half * 256;
    float bb = kv_b[yoff + tid];
    float acc[4];
#pragma unroll
    for (int i = 0; i < 4; i++) acc[i] = bb;

#pragma unroll 8
    for (int kk = 0; kk < DIM; kk++) {
        float w = kv_w[(size_t)kk * 512 + yoff + tid];
#pragma unroll
        for (int i = 0; i < 4; i++) acc[i] = fmaf(xr[i][kk], w, acc[i]);
    }

#pragma unroll
    for (int i = 0; i < 4; i++) {
        int bp = bp0 + i;
        int b = bp / PLEN, p = bp % PLEN;
        size_t dst = (((size_t)(b * HEADS + wp)) * PLEN + p) * HD + lane;
        if (half == 0) {
            float ss = acc[i] * acc[i];
#pragma unroll
            for (int o = 16; o; o >>= 1) ss += __shfl_xor_sync(0xffffffffu, ss, o);
            g_kp[dst] = acc[i] / fmaxf(sqrtf(ss), 1e-12f);
        } else {
            g_vp[dst] = acc[i];
        }
    }
}

// ---------------- fused attention: quad-pixel, tiled halo, no-max softmax ----------------
constexpr int TR = 4, TC = 28, HR = 6, HC = 30;
constexpr int KST = 36;
constexpr int QST = 36;

struct AttnSmem {
    float k_halo[HR * HC * KST];
    float v_halo[HR * HC * KST];
    float kp[PLEN * KST];
    float vp[PLEN * KST];
    float lt[LOCAL * KST];
    float q  [8][4][QST];
    float qn [8][4][QST];
    float a9 [8][4][12];
    float ap [8][4][52];
    float rpb[LOCAL];
    float lb [LOCAL];
};

__global__ __launch_bounds__(256, 2)
void attn_kernel(const float* __restrict__ rpb_local,
                 const float* __restrict__ ltok,
                 const float* __restrict__ lbias)
{
    extern __shared__ char smem_raw[];
    AttnSmem& sm = *reinterpret_cast<AttnSmem*>(smem_raw);

    int bh = blockIdx.x;
    int b = bh / HEADS, h = bh % HEADS;
    int ty = blockIdx.y;
    int tr0 = (ty % 14) * TR;
    int tc0 = (ty / 14) * TC;
    int tid = threadIdx.x, warp = tid >> 5, lane = tid & 31;

    const float* k_base = g_k + (size_t)bh * N0 * HD;
    const float* v_base = g_v + (size_t)bh * N0 * HD;

    for (int f = tid; f < HR * HC * 16; f += 256) {
        int row = f >> 4;
        int rem = f & 15;
        int mat = rem >> 3;
        int c4  = rem & 7;
        int hr = row / HC, hc = row % HC;
        int gr = tr0 - 1 + hr, gc = tc0 - 1 + hc;
        bool ok = (gr >= 0 && gr < H0 && gc >= 0 && gc < W0);
        float4 val = make_float4(0.f, 0.f, 0.f, 0.f);
        if (ok) {
            const float* src = mat ? v_base : k_base;
            val = *reinterpret_cast<const float4*>(&src[(size_t)(gr * W0 + gc) * HD + c4 * 4]);
        }
        float* dst = mat ? sm.v_halo : sm.k_halo;
        *reinterpret_cast<float4*>(&dst[row * KST + c4 * 4]) = val;
    }
    {
        const float* kpsrc = g_kp + (size_t)bh * PLEN * HD;
        const float* vpsrc = g_vp + (size_t)bh * PLEN * HD;
        for (int f = tid; f < PLEN * 16; f += 256) {
            int m = f >> 4, rem = f & 15, mat = rem >> 3, c4 = rem & 7;
            const float* src = mat ? vpsrc : kpsrc;
            float4 val = *reinterpret_cast<const float4*>(&src[(size_t)m * HD + c4 * 4]);
            float* dst = mat ? sm.vp : sm.kp;
            *reinterpret_cast<float4*>(&dst[m * KST + c4 * 4]) = val;
        }
    }
    for (int i = tid; i < HD * LOCAL; i += 256) {
        int d = i / LOCAL, l = i % LOCAL;
        sm.lt[l * KST + d] = ltok[h * HD * LOCAL + i];
    }
    if (tid < LOCAL) {
        sm.rpb[tid] = rpb_local[h * LOCAL + tid];
        sm.lb[tid]  = lbias[h * LOCAL + tid];
    }
    __syncthreads();

    // hoist pooled-V column (this lane's dim) into registers
    float vpreg[PLEN];
#pragma unroll
    for (int m = 0; m < PLEN; m++) vpreg[m] = sm.vp[m * KST + lane];

    const float* qs_base = g_qs + (size_t)bh * N0 * HD;
    const float* qn_base = g_qn + (size_t)bh * N0 * HD;
    const float* pb_base = g_pb + (size_t)h * N0 * 52;

    int lr = warp & 3;
    int colbase = (warp >> 2) * 14;
    int pi = tr0 + lr;

    int grp  = lane >> 4;
    int ll   = lane & 15;
    bool lact = ll < LOCAL;
    int lidx = lact ? ll : 0;
    int ldi = lidx / 3 - 1, ldj = lidx % 3 - 1;
    int mi1 = (lane < 17) ? lane + 32 : 0;

    for (int j = 0; j < 4; j++) {
        int lc[4];
#pragma unroll
        for (int i = 0; i < 4; i++) lc[i] = colbase + j * 4 + i;
        if (j == 3) { lc[2] = lc[0]; lc[3] = lc[1]; }
        int n[4], pj[4];
#pragma unroll
        for (int i = 0; i < 4; i++) { pj[i] = tc0 + lc[i]; n[i] = pi * W0 + pj[i]; }

#pragma unroll
        for (int i = 0; i < 4; i++) {
            sm.q [warp][i][lane] = qs_base[(size_t)n[i] * HD + lane];
            sm.qn[warp][i][lane] = qn_base[(size_t)n[i] * HD + lane];
        }
        // prefetch pool biases (L2 latency hidden under score loop)
        float pb0[4], pb1[4];
#pragma unroll
        for (int i = 0; i < 4; i++) {
            const float* pbp = &pb_base[(size_t)n[i] * 52];
            pb0[i] = pbp[lane];
            pb1[i] = (lane < 17) ? pbp[32 + lane] : 0.f;
        }
        __syncwarp();

        int pxA = grp, pxB = 2 + grp;
        int hrowA = lact ? ((lr + 1 + ldi) * HC + (lc[pxA] + 1 + ldj)) : 0;
        int hrowB = lact ? ((lr + 1 + ldi) * HC + (lc[pxB] + 1 + ldj)) : 0;

        float sp0[4] = {0,0,0,0}, sp1[4] = {0,0,0,0};
        float s9A = 0.f, s9B = 0.f, tlE = 0.f, tlO = 0.f;

#pragma unroll
        for (int c = 0; c < 8; c++) {
            float4 q0 = *reinterpret_cast<const float4*>(&sm.q[warp][0][c * 4]);
            float4 q1 = *reinterpret_cast<const float4*>(&sm.q[warp][1][c * 4]);
            float4 q2 = *reinterpret_cast<const float4*>(&sm.q[warp][2][c * 4]);
            float4 q3 = *reinterpret_cast<const float4*>(&sm.q[warp][3][c * 4]);
            float4 qnE = *reinterpret_cast<const float4*>(&sm.qn[warp][grp][c * 4]);
            float4 qnO = *reinterpret_cast<const float4*>(&sm.qn[warp][2 + grp][c * 4]);
            float4 kA = *reinterpret_cast<const float4*>(&sm.kp[lane * KST + c * 4]);
            float4 kB = *reinterpret_cast<const float4*>(&sm.kp[mi1 * KST + c * 4]);
            float4 k9A = *reinterpret_cast<const float4*>(&sm.k_halo[hrowA * KST + c * 4]);
            float4 k9B = *reinterpret_cast<const float4*>(&sm.k_halo[hrowB * KST + c * 4]);
            float4 l4 = *reinterpret_cast<const float4*>(&sm.lt[lidx * KST + c * 4]);

            DOT4(sp0[0], kA, q0); DOT4(sp0[1], kA, q1);
            DOT4(sp0[2], kA, q2); DOT4(sp0[3], kA, q3);
            DOT4(sp1[0], kB, q0); DOT4(sp1[1], kB, q1);
            DOT4(sp1[2], kB, q2); DOT4(sp1[3], kB, q3);
            float4 qA = grp ? q1 : q0;
            float4 qB = grp ? q3 : q2;
            DOT4(s9A, k9A, qA);
            DOT4(s9B, k9B, qB);
            DOT4(tlE, l4, qnE);
            DOT4(tlO, l4, qnO);
        }

        bool okA = lact && (pi + ldi >= 0) && (pi + ldi < H0) &&
                   (pj[pxA] + ldj >= 0) && (pj[pxA] + ldj < W0);
        bool okB = lact && (pi + ldi >= 0) && (pi + ldi < H0) &&
                   (pj[pxB] + ldj >= 0) && (pj[pxB] + ldj < W0);
        // no-max softmax: |score| <= ~40, exp stays in fp32 range
        float e9A = okA ? __expf(s9A + sm.rpb[lidx]) : 0.f;
        float e9B = okB ? __expf(s9B + sm.rpb[lidx]) : 0.f;

        float e0[4], e1[4], el[4], inv[4];
#pragma unroll
        for (int i = 0; i < 4; i++) {
            e0[i] = __expf(sp0[i] + pb0[i]);
            e1[i] = (lane < 17) ? __expf(sp1[i] + pb1[i]) : 0.f;
            el[i] = ((i & 1) == grp) ? (i < 2 ? e9A : e9B) : 0.f;
            float s = e0[i] + e1[i] + el[i];
#pragma unroll
            for (int o = 16; o; o >>= 1) s += __shfl_xor_sync(0xffffffffu, s, o);
            inv[i] = 1.f / s;
        }

#pragma unroll
        for (int i = 0; i < 4; i++) {
            sm.ap[warp][i][lane] = e0[i] * inv[i];
            if (lane < 17) sm.ap[warp][i][32 + lane] = e1[i] * inv[i];
        }
        if (lact) {
            sm.a9[warp][pxA][lidx] = e9A * inv[pxA] + tlE + sm.lb[lidx];
            sm.a9[warp][pxB][lidx] = e9B * inv[pxB] + tlO + sm.lb[lidx];
        }
        __syncwarp();

        float out[4] = {0.f, 0.f, 0.f, 0.f};
#pragma unroll
        for (int g = 0; g < 12; g++) {
            float4 a0 = *reinterpret_cast<const float4*>(&sm.ap[warp][0][g * 4]);
            float4 a1 = *reinterpret_cast<const float4*>(&sm.ap[warp][1][g * 4]);
            float4 a2 = *reinterpret_cast<const float4*>(&sm.ap[warp][2][g * 4]);
            float4 a3 = *reinterpret_cast<const float4*>(&sm.ap[warp][3][g * 4]);
            float v0 = vpreg[g * 4 + 0];
            float v1 = vpreg[g * 4 + 1];
            float v2 = vpreg[g * 4 + 2];
            float v3 = vpreg[g * 4 + 3];
            out[0] += a0.x * v0 + a0.y * v1 + a0.z * v2 + a0.w * v3;
            out[1] += a1.x * v0 + a1.y * v1 + a1.z * v2 + a1.w * v3;
            out[2] += a2.x * v0 + a2.y * v1 + a2.z * v2 + a2.w * v3;
            out[3] += a3.x * v0 + a3.y * v1 + a3.z * v2 + a3.w * v3;
        }
        {
            float v = vpreg[48];
#pragma unroll
            for (int i = 0; i < 4; i++) out[i] += sm.ap[warp][i][48] * v;
        }
        int hb[4];
#pragma unroll
        for (int i = 0; i < 4; i++) hb[i] = (lr + 1) * HC + lc[i] + 1;
#pragma unroll
        for (int l = 0; l < LOCAL; l++) {
            int roff = (l / 3 - 1) * HC + (l % 3 - 1);
#pragma unroll
            for (int i = 0; i < 4; i++) {
                out[i] += sm.a9[warp][i][l] * sm.v_halo[(hb[i] + roff) * KST + lane];
            }
        }

#pragma unroll
        for (int i = 0; i < 4; i++) {
            if (j == 3 && i >= 2) break;
            float o = out[i];
            float nb = __shfl_down_sync(0xffffffffu, o, 1);
            if ((lane & 1) == 0) {
                uint32_t hi, lo;
                split2(o, nb, hi, lo);
                size_t base = ((size_t)(b * N0 + n[i])) * 128 + h * 16 + (lane >> 1);
                g_xoH[base] = hi;
                g_xoL[base] = lo;
            }
        }
        __syncwarp();
    }
}

// ---------------- launch ----------------
extern "C" void kernel_launch(void* const* d_in, const int* in_sizes, int n_in,
                              void* d_out, int out_size)
{
    const float* x      = (const float*)d_in[0];
    const float* sls    = (const float*)d_in[1];
    const float* rct    = (const float*)d_in[2];
    const float* q_w    = (const float*)d_in[3];
    const float* q_b    = (const float*)d_in[4];
    const float* qe     = (const float*)d_in[5];
    const float* temp   = (const float*)d_in[6];
    const float* kv_w   = (const float*)d_in[7];
    const float* kv_b   = (const float*)d_in[8];
    const float* sr_w   = (const float*)d_in[9];
    const float* sr_b   = (const float*)d_in[10];
    const float* norm_g = (const float*)d_in[11];
    const float* norm_b = (const float*)d_in[12];
    const float* fc1_w  = (const float*)d_in[13];
    const float* fc1_b  = (const float*)d_in[14];
    const float* fc2_w  = (const float*)d_in[15];
    const float* fc2_b  = (const float*)d_in[16];
    const float* rpb    = (const float*)d_in[17];
    const float* lt     = (const float*)d_in[18];
    const float* lb     = (const float*)d_in[19];
    const float* proj_w = (const float*)d_in[20];
    const float* proj_b = (const float*)d_in[21];
    const int*   rpi    = (const int*)d_in[22];
    float* out = (float*)d_out;

    cudaFuncSetAttribute(gemm_mma_kernel<0>, cudaFuncAttributeMaxDynamicSharedMemorySize, GEMM_SMEM);
    cudaFuncSetAttribute(gemm_mma_kernel<1>, cudaFuncAttributeMaxDynamicSharedMemorySize, GEMM_SMEM);
    cudaFuncSetAttribute(attn_kernel, cudaFuncAttributeMaxDynamicSharedMemorySize, (int)sizeof(AttnSmem));

    // 1) fused pre: convert x + convert W + cpb table
    pre_kernel<<<NBLK_CX + NBLK_CW + NBLK_CPB, 256>>>(x, q_w, kv_w, sr_w, proj_w,
                                                      rct, fc1_w, fc1_b, fc2_w, fc2_b);

    // 2) fused GEMM1 (128x64 tiles, k64 chunks, 2-stage, 2 CTAs/SM)
    dim3 g1(MROWS / 128, 1024 / 64);
    gemm_mma_kernel<0><<<g1, 256, GEMM_SMEM>>>(q_b, kv_b, sr_b, qe, temp, sls, nullptr);

    // 3) fused mid: pool+LN+kvp and pool_bias precompute
    mid_kernel<<<NBLK_PK + NBLK_PB, 256>>>(norm_g, norm_b, kv_w, kv_b, rpi);

    // 4) fused attention (profiled slot)
    attn_kernel<<<dim3(B_ * HEADS, 28), 256, sizeof(AttnSmem)>>>(rpb, lt, lb);

    // 5) proj GEMM -> d_out
    dim3 g7(MROWS / 128, 256 / 64);
    gemm_mma_kernel<1><<<g7, 256, GEMM_SMEM>>>(proj_b, nullptr, nullptr, nullptr, nullptr, nullptr, out);
}

// round 14
// speedup vs baseline: 1.0533x; 1.0533x over previous
#include <cuda_runtime.h>
#include <cuda_bf16.h>
#include <math.h>
#include <stdint.h>

// ---------------- problem constants (all static) ----------------
constexpr int B_    = 8;
constexpr int H0    = 56;
constexpr int W0    = 56;
constexpr int N0    = H0 * W0;        // 3136
constexpr int DIM   = 256;
constexpr int HEADS = 8;
constexpr int HD    = 32;
constexpr int LOCAL = 9;
constexpr int PW    = 7;
constexpr int PLEN  = 49;
constexpr int LTAB  = 4096;
constexpr int MROWS = B_ * N0;        // 25088

// ---------------- scratch (device globals; no allocs) ----------------
__device__ float g_qs[B_*HEADS*N0*HD];
__device__ float g_qn[B_*HEADS*N0*HD];
__device__ float g_k [B_*HEADS*N0*HD];
__device__ float g_v [B_*HEADS*N0*HD];
__device__ float g_xs[B_*N0*DIM];
__device__ float g_kp[B_*HEADS*PLEN*HD];
__device__ float g_vp[B_*HEADS*PLEN*HD];
__device__ float g_tab[LTAB*HEADS];
__device__ float g_pb[HEADS*N0*52];      // precomputed pool_bias [h][n][m]

// packed bf16 hi/lo operands (u32 = 2 bf16 along k)
__device__ uint32_t g_xH [MROWS*128];
__device__ uint32_t g_xL [MROWS*128];
__device__ uint32_t g_xoH[MROWS*128];
__device__ uint32_t g_xoL[MROWS*128];
__device__ uint32_t g_wH [1280*128];     // fused W [col][k2]: q|k|v|sr|proj
__device__ uint32_t g_wL [1280*128];

// ---------------- helpers ----------------
__device__ __forceinline__ uint32_t pack_bf2(__nv_bfloat16 x, __nv_bfloat16 y) {
    __nv_bfloat162 t; t.x = x; t.y = y;
    return *reinterpret_cast<uint32_t*>(&t);
}
__device__ __forceinline__ void split2(float x, float y, uint32_t& hi, uint32_t& lo) {
    __nv_bfloat16 xh = __float2bfloat16_rn(x);
    __nv_bfloat16 yh = __float2bfloat16_rn(y);
    float xr = x - __bfloat162float(xh);
    float yr = y - __bfloat162float(yh);
    hi = pack_bf2(xh, yh);
    lo = pack_bf2(__float2bfloat16_rn(xr), __float2bfloat16_rn(yr));
}

#define MMA16816(d, a0,a1,a2,a3, b0,b1) \
    asm volatile("mma.sync.aligned.m16n8k16.row.col.f32.bf16.bf16.f32 " \
        "{%0,%1,%2,%3},{%4,%5,%6,%7},{%8,%9},{%0,%1,%2,%3};" \
        : "+f"(d[0]), "+f"(d[1]), "+f"(d[2]), "+f"(d[3]) \
        : "r"(a0), "r"(a1), "r"(a2), "r"(a3), "r"(b0), "r"(b1))

#define LDSM4(r, addr) \
    asm volatile("ldmatrix.sync.aligned.m8n8.x4.shared.b16 {%0,%1,%2,%3}, [%4];" \
        : "=r"((r)[0]), "=r"((r)[1]), "=r"((r)[2]), "=r"((r)[3]) : "r"(addr))

__device__ __forceinline__ void cp16(uint32_t dst, const void* src) {
    asm volatile("cp.async.cg.shared.global [%0], [%1], 16;" :: "r"(dst), "l"(src));
}

#define DOT4(acc, a, b) (acc) += (a).x*(b).x + (a).y*(b).y + (a).z*(b).z + (a).w*(b).w

// ---------------- conversion kernels ----------------
__global__ __launch_bounds__(256)
void convert_x_kernel(const float* __restrict__ x)
{
    int i = blockIdx.x * 256 + threadIdx.x;
    float4 v = reinterpret_cast<const float4*>(x)[i];
    uint32_t h0, l0, h1, l1;
    split2(v.x, v.y, h0, l0);
    split2(v.z, v.w, h1, l1);
    g_xH[i * 2] = h0; g_xH[i * 2 + 1] = h1;
    g_xL[i * 2] = l0; g_xL[i * 2 + 1] = l1;
}

__global__ __launch_bounds__(256)
void convert_w_kernel(const float* __restrict__ q_w, const float* __restrict__ kv_w,
                      const float* __restrict__ sr_w, const float* __restrict__ proj_w)
{
    int idx = blockIdx.x * 256 + threadIdx.x;        // 1280*128
    int c = idx >> 7, k2 = idx & 127;
    float f0, f1;
    if (c < 256)       { f0 = q_w [(2*k2)   * 256 + c];        f1 = q_w [(2*k2+1) * 256 + c];        }
    else if (c < 768)  { f0 = kv_w[(2*k2)   * 512 + c - 256];  f1 = kv_w[(2*k2+1) * 512 + c - 256];  }
    else if (c < 1024) { f0 = sr_w[(2*k2)   * 256 + c - 768];  f1 = sr_w[(2*k2+1) * 256 + c - 768];  }
    else               { f0 = proj_w[(2*k2) * 256 + c - 1024]; f1 = proj_w[(2*k2+1) * 256 + c - 1024]; }
    uint32_t h, l;
    split2(f0, f1, h, l);
    g_wH[idx] = h; g_wL[idx] = l;
}

__global__ void cpb_kernel(const float* __restrict__ rct,
                           const float* __restrict__ w1, const float* __restrict__ b1,
                           const float* __restrict__ w2, const float* __restrict__ b2)
{
    int gw = (blockIdx.x * blockDim.x + threadIdx.x) >> 5;
    int lane = threadIdx.x & 31;
    if (gw >= LTAB) return;
    float r0 = rct[gw * 2], r1 = rct[gw * 2 + 1];
    float acc[HEADS];
#pragma unroll
    for (int h = 0; h < HEADS; h++) acc[h] = 0.f;
    for (int j = lane; j < 512; j += 32) {
        float hv = fmaxf(r0 * w1[j] + r1 * w1[512 + j] + b1[j], 0.f);
#pragma unroll
        for (int h = 0; h < HEADS; h++) acc[h] += hv * w2[j * HEADS + h];
    }
#pragma unroll
    for (int h = 0; h < HEADS; h++)
#pragma unroll
        for (int o = 16; o; o >>= 1) acc[h] += __shfl_xor_sync(0xffffffffu, acc[h], o);
    if (lane == 0) {
#pragma unroll
        for (int h = 0; h < HEADS; h++) g_tab[gw * HEADS + h] = acc[h] + b2[h];
    }
}

__global__ __launch_bounds__(256)
void pb_kernel(const int* __restrict__ rpi)
{
    int idx = blockIdx.x * 256 + threadIdx.x;
    if (idx >= HEADS * N0 * PLEN) return;
    int m = idx % PLEN;
    int hn = idx / PLEN;
    int h = hn / N0, n = hn % N0;
    g_pb[(size_t)hn * 52 + m] = g_tab[rpi[n * PLEN + m] * HEADS + h];
}

// ---------------- bf16x3 tensor-core GEMM, 128x64 tile, 3-stage pipeline (R12) ----------------
constexpr int LDU = 20;
constexpr uint32_t SM_AL = 10240;
constexpr uint32_t SM_BH = 20480;
constexpr uint32_t SM_BL = 25600;
constexpr uint32_t SM_STAGE = 30720;
constexpr int GEMM_SMEM = 92160;         // 3 stages

template<int MODE>
__global__ __launch_bounds__(256, 2)
void gemm_mma_kernel(const float* __restrict__ bq, const float* __restrict__ bkv,
                     const float* __restrict__ bsr,
                     const float* __restrict__ qe, const float* __restrict__ temp,
                     const float* __restrict__ sls,
                     float* __restrict__ Out)
{
    extern __shared__ uint32_t sm_u[];
    uint32_t sbase = (uint32_t)__cvta_generic_to_shared(sm_u);

    const uint32_t* AH = MODE ? g_xoH : g_xH;
    const uint32_t* AL = MODE ? g_xoL : g_xL;

    int tid  = threadIdx.x;
    int lane = tid & 31;
    int warp = tid >> 5;
    int wm   = warp >> 1;
    int wn   = warp & 1;

    int m0    = blockIdx.x * 128;
    int col0  = blockIdx.y * 64;
    int bcol0 = col0 + (MODE ? 1024 : 0);

    int lrowA = tid >> 1;
    int loffA = (tid & 1) * 8;
    uint32_t dstA = (uint32_t)(lrowA * LDU + loffA) * 4;
    int lrowB = tid >> 2;
    int loffB = (tid & 3) * 4;
    uint32_t dstB = (uint32_t)(lrowB * LDU + loffB) * 4;

    const uint32_t* aHp = &AH  [(size_t)(m0 + lrowA)    * 128 + loffA];
    const uint32_t* aLp = &AL  [(size_t)(m0 + lrowA)    * 128 + loffA];
    const uint32_t* bHp = &g_wH[(size_t)(bcol0 + lrowB) * 128 + loffB];
    const uint32_t* bLp = &g_wL[(size_t)(bcol0 + lrowB) * 128 + loffB];

    int aRow  = wm * 32 + (lane & 7) + ((lane >> 3) & 1) * 8;
    int aCol4 = ((lane >> 4) & 1) * 4;
    uint32_t aoff[2][2];
#pragma unroll
    for (int mt = 0; mt < 2; mt++)
#pragma unroll
        for (int s = 0; s < 2; s++)
            aoff[mt][s] = (uint32_t)(((aRow + mt * 16) * LDU) + s * 8 + aCol4) * 4;
    int bRow  = wn * 32 + (lane & 7);
    int bCol4 = ((lane >> 3) & 3) * 4;
    uint32_t boff[4];
#pragma unroll
    for (int nt = 0; nt < 4; nt++)
        boff[nt] = (uint32_t)(((bRow + nt * 8) * LDU) + bCol4) * 4;

    float acc[2][4][4];
#pragma unroll
    for (int i = 0; i < 2; i++)
#pragma unroll
        for (int j = 0; j < 4; j++)
#pragma unroll
            for (int e = 0; e < 4; e++) acc[i][j][e] = 0.f;

#define ISSUE_STAGE(it, buf) do { \
    uint32_t st_ = sbase + (uint32_t)(buf) * SM_STAGE; \
    cp16(st_ + dstA,              aHp + (it) * 16); \
    cp16(st_ + dstA + 16,         aHp + (it) * 16 + 4); \
    cp16(st_ + SM_AL + dstA,      aLp + (it) * 16); \
    cp16(st_ + SM_AL + dstA + 16, aLp + (it) * 16 + 4); \
    cp16(st_ + SM_BH + dstB,      bHp + (it) * 16); \
    cp16(st_ + SM_BL + dstB,      bLp + (it) * 16); \
    asm volatile("cp.async.commit_group;"); \
} while (0)

    ISSUE_STAGE(0, 0);
    ISSUE_STAGE(1, 1);

#pragma unroll
    for (int it = 0; it < 8; it++) {
        if (it < 7) {
            asm volatile("cp.async.wait_group 1;");
        } else {
            asm volatile("cp.async.wait_group 0;");
        }
        __syncthreads();
        {
            uint32_t st = sbase + (uint32_t)(it % 3) * SM_STAGE;
            uint32_t bHf[4][4], bLf[4][4];
#pragma unroll
            for (int nt = 0; nt < 4; nt++) {
                LDSM4(bHf[nt], st + SM_BH + boff[nt]);
                LDSM4(bLf[nt], st + SM_BL + boff[nt]);
            }
#pragma unroll
            for (int s = 0; s < 2; s++) {
                uint32_t aHf[2][4], aLf[2][4];
#pragma unroll
                for (int mt = 0; mt < 2; mt++) {
                    LDSM4(aHf[mt], st + aoff[mt][s]);
                    LDSM4(aLf[mt], st + SM_AL + aoff[mt][s]);
                }
#pragma unroll
                for (int mt = 0; mt < 2; mt++)
#pragma unroll
                    for (int nt = 0; nt < 4; nt++) {
                        MMA16816(acc[mt][nt], aHf[mt][0], aHf[mt][1], aHf[mt][2], aHf[mt][3],
                                 bHf[nt][2*s], bHf[nt][2*s+1]);
                        MMA16816(acc[mt][nt], aHf[mt][0], aHf[mt][1], aHf[mt][2], aHf[mt][3],
                                 bLf[nt][2*s], bLf[nt][2*s+1]);
                        MMA16816(acc[mt][nt], aLf[mt][0], aLf[mt][1], aLf[mt][2], aLf[mt][3],
                                 bHf[nt][2*s], bHf[nt][2*s+1]);
                    }
            }
        }
        if (it < 6) ISSUE_STAGE(it + 2, (it + 2) % 3);
    }
#undef ISSUE_STAGE

    // ---------------- epilogue ----------------
    if (MODE == 1) {
#pragma unroll
        for (int mt = 0; mt < 2; mt++) {
            int r0 = m0 + wm * 32 + mt * 16 + (lane >> 2);
#pragma unroll
            for (int nt = 0; nt < 4; nt++) {
                int c0 = col0 + wn * 32 + nt * 8 + (lane & 3) * 2;
                Out[(size_t)r0 * DIM + c0]           = acc[mt][nt][0] + bq[c0];
                Out[(size_t)r0 * DIM + c0 + 1]       = acc[mt][nt][1] + bq[c0 + 1];
                Out[(size_t)(r0 + 8) * DIM + c0]     = acc[mt][nt][2] + bq[c0];
                Out[(size_t)(r0 + 8) * DIM + c0 + 1] = acc[mt][nt][3] + bq[c0 + 1];
            }
        }
        return;
    }

    int strip = (col0 + wn * 32) >> 5;
#pragma unroll
    for (int mt = 0; mt < 2; mt++)
#pragma unroll
        for (int nt = 0; nt < 4; nt++) {
            int c = col0 + wn * 32 + nt * 8 + (lane & 3) * 2;
            float b0, b1;
            if (c < 256)      { b0 = bq[c];        b1 = bq[c + 1];    }
            else if (c < 768) { b0 = bkv[c - 256]; b1 = bkv[c - 255]; }
            else              { b0 = bsr[c - 768]; b1 = bsr[c - 767]; }
            acc[mt][nt][0] += b0; acc[mt][nt][1] += b1;
            acc[mt][nt][2] += b0; acc[mt][nt][3] += b1;
        }

    if (strip < 16) {
        int h = strip & 7;
        bool isq = strip < 8;
        float spsls = 0.f;
        if (isq) spsls = log1pf(expf(temp[h])) * sls[0];
#pragma unroll
        for (int mt = 0; mt < 2; mt++) {
            float ss0 = 0.f, ss1 = 0.f;
#pragma unroll
            for (int nt = 0; nt < 4; nt++) {
                ss0 += acc[mt][nt][0] * acc[mt][nt][0] + acc[mt][nt][1] * acc[mt][nt][1];
                ss1 += acc[mt][nt][2] * acc[mt][nt][2] + acc[mt][nt][3] * acc[mt][nt][3];
            }
            ss0 += __shfl_xor_sync(0xffffffffu, ss0, 1);
            ss0 += __shfl_xor_sync(0xffffffffu, ss0, 2);
            ss1 += __shfl_xor_sync(0xffffffffu, ss1, 1);
            ss1 += __shfl_xor_sync(0xffffffffu, ss1, 2);
            float inv0 = 1.f / fmaxf(sqrtf(ss0), 1e-12f);
            float inv1 = 1.f / fmaxf(sqrtf(ss1), 1e-12f);
            int r0 = m0 + wm * 32 + mt * 16 + (lane >> 2);
            int b0i = r0 / N0, n0i = r0 % N0;
            int b1i = (r0 + 8) / N0, n1i = (r0 + 8) % N0;
            size_t base0 = (((size_t)(b0i * HEADS + h)) * N0 + n0i) * HD;
            size_t base1 = (((size_t)(b1i * HEADS + h)) * N0 + n1i) * HD;
#pragma unroll
            for (int nt = 0; nt < 4; nt++) {
                int d0 = (wn * 32 + nt * 8 + (lane & 3) * 2) & 31;
#pragma unroll
                for (int p = 0; p < 2; p++) {
                    int d = d0 + p;
                    float v0 = acc[mt][nt][p]     * inv0;
                    float v1 = acc[mt][nt][2 + p] * inv1;
                    if (isq) {
                        float e = qe[h * HD + d];
                        g_qn[base0 + d] = v0;
                        g_qn[base1 + d] = v1;
                        g_qs[base0 + d] = (v0 + e) * spsls;
                        g_qs[base1 + d] = (v1 + e) * spsls;
                    } else {
                        g_k[base0 + d] = v0;
                        g_k[base1 + d] = v1;
                    }
                }
            }
        }
    } else if (strip < 24) {
        int h = strip & 7;
#pragma unroll
        for (int mt = 0; mt < 2; mt++) {
            int r0 = m0 + wm * 32 + mt * 16 + (lane >> 2);
            int ba = r0 / N0, na = r0 % N0;
            int bb = (r0 + 8) / N0, nb = (r0 + 8) % N0;
            size_t base0 = (((size_t)(ba * HEADS + h)) * N0 + na) * HD;
            size_t base1 = (((size_t)(bb * HEADS + h)) * N0 + nb) * HD;
#pragma unroll
            for (int nt = 0; nt < 4; nt++) {
                int d = (wn * 32 + nt * 8 + (lane & 3) * 2) & 31;
                g_v[base0 + d]     = acc[mt][nt][0];
                g_v[base0 + d + 1] = acc[mt][nt][1];
                g_v[base1 + d]     = acc[mt][nt][2];
                g_v[base1 + d + 1] = acc[mt][nt][3];
            }
        }
    } else {
#pragma unroll
        for (int mt = 0; mt < 2; mt++) {
            int r0 = m0 + wm * 32 + mt * 16 + (lane >> 2);
            int ba = r0 / N0, na = r0 % N0;
            int bb = (r0 + 8) / N0, nb = (r0 + 8) % N0;
#pragma unroll
            for (int nt = 0; nt < 4; nt++) {
                int cc = (wn * 32 + nt * 8 + (lane & 3) * 2) + col0 - 768;
#pragma unroll
                for (int p = 0; p < 2; p++) {
                    float v0 = acc[mt][nt][p];
                    float v1 = acc[mt][nt][2 + p];
                    g_xs[((size_t)(ba * N0 + na)) * DIM + cc + p] =
                        0.5f * v0 * (1.f + erff(v0 * 0.70710678118654752f));
                    g_xs[((size_t)(bb * N0 + nb)) * DIM + cc + p] =
                        0.5f * v1 * (1.f + erff(v1 * 0.70710678118654752f));
                }
            }
        }
    }
}

// ---------------- fused pool + LN + kvp ----------------
__global__ __launch_bounds__(256)
void poolkvp_kernel(const float* __restrict__ gamma, const float* __restrict__ beta,
                    const float* __restrict__ kv_w, const float* __restrict__ kv_b)
{
    __shared__ float xr[4][DIM];
    __shared__ float redm[4][8], redv[4][8];
    int bp0 = blockIdx.x * 4;
    int half = blockIdx.y;
    int tid = threadIdx.x, lane = tid & 31, wp = tid >> 5;

    float sv[4];
#pragma unroll
    for (int i = 0; i < 4; i++) {
        int bp = bp0 + i, b = bp / PLEN, p = bp % PLEN;
        int pi = p / PW, pj = p % PW;
        float s = 0.f;
#pragma unroll
        for (int r = 0; r < 8; r++)
#pragma unroll
            for (int c = 0; c < 8; c++)
                s += g_xs[((size_t)(b * N0 + (pi * 8 + r) * W0 + pj * 8 + c)) * DIM + tid];
        sv[i] = s * (1.f / 64.f);
    }
#pragma unroll
    for (int i = 0; i < 4; i++) {
        float m = sv[i];
#pragma unroll
        for (int o = 16; o; o >>= 1) m += __shfl_xor_sync(0xffffffffu, m, o);
        if (lane == 0) redm[i][wp] = m;
    }
    __syncthreads();
    float dv[4];
#pragma unroll
    for (int i = 0; i < 4; i++) {
        float mean = 0.f;
#pragma unroll
        for (int w = 0; w < 8; w++) mean += redm[i][w];
        mean *= (1.f / 256.f);
        dv[i] = sv[i] - mean;
        float v2 = dv[i] * dv[i];
#pragma unroll
        for (int o = 16; o; o >>= 1) v2 += __shfl_xor_sync(0xffffffffu, v2, o);
        if (lane == 0) redv[i][wp] = v2;
    }
    __syncthreads();
#pragma unroll
    for (int i = 0; i < 4; i++) {
        float var = 0.f;
#pragma unroll
        for (int w = 0; w < 8; w++) var += redv[i][w];
        var *= (1.f / 256.f);
        xr[i][tid] = dv[i] * rsqrtf(var + 1e-5f) * gamma[tid] + beta[tid];
    }
    __syncthreads();

    int yoff = half * 256;
    float bb = kv_b[yoff + tid];
    float acc[4];
#pragma unroll
    for (int i = 0; i < 4; i++) acc[i] = bb;

#pragma unroll 8
    for (int kk = 0; kk < DIM; kk++) {
        float w = kv_w[(size_t)kk * 512 + yoff + tid];
#pragma unroll
        for (int i = 0; i < 4; i++) acc[i] = fmaf(xr[i][kk], w, acc[i]);
    }

#pragma unroll
    for (int i = 0; i < 4; i++) {
        int bp = bp0 + i;
        int b = bp / PLEN, p = bp % PLEN;
        size_t dst = (((size_t)(b * HEADS + wp)) * PLEN + p) * HD + lane;
        if (half == 0) {
            float ss = acc[i] * acc[i];
#pragma unroll
            for (int o = 16; o; o >>= 1) ss += __shfl_xor_sync(0xffffffffu, ss, o);
            g_kp[dst] = acc[i] / fmaxf(sqrtf(ss), 1e-12f);
        } else {
            g_vp[dst] = acc[i];
        }
    }
}

// ---------------- fused attention: quad-pixel, tiled halo, no-max softmax ----------------
constexpr int TR = 4, TC = 28, HR = 6, HC = 30;
constexpr int KST = 36;
constexpr int QST = 36;

struct AttnSmem {
    float k_halo[HR * HC * KST];
    float v_halo[HR * HC * KST];
    float kp[PLEN * KST];
    float vp[PLEN * KST];
    float lt[LOCAL * KST];
    float q  [8][4][QST];
    float qn [8][4][QST];
    float a9 [8][4][12];
    float ap [8][4][52];
    float rpb[LOCAL];
    float lb [LOCAL];
};

__global__ __launch_bounds__(256, 2)
void attn_kernel(const float* __restrict__ rpb_local,
                 const float* __restrict__ ltok,
                 const float* __restrict__ lbias)
{
    extern __shared__ char smem_raw[];
    AttnSmem& sm = *reinterpret_cast<AttnSmem*>(smem_raw);

    int bh = blockIdx.x;
    int b = bh / HEADS, h = bh % HEADS;
    int ty = blockIdx.y;
    int tr0 = (ty % 14) * TR;
    int tc0 = (ty / 14) * TC;
    int tid = threadIdx.x, warp = tid >> 5, lane = tid & 31;

    const float* k_base = g_k + (size_t)bh * N0 * HD;
    const float* v_base = g_v + (size_t)bh * N0 * HD;

    for (int f = tid; f < HR * HC * 16; f += 256) {
        int row = f >> 4;
        int rem = f & 15;
        int mat = rem >> 3;
        int c4  = rem & 7;
        int hr = row / HC, hc = row % HC;
        int gr = tr0 - 1 + hr, gc = tc0 - 1 + hc;
        bool ok = (gr >= 0 && gr < H0 && gc >= 0 && gc < W0);
        float4 val = make_float4(0.f, 0.f, 0.f, 0.f);
        if (ok) {
            const float* src = mat ? v_base : k_base;
            val = *reinterpret_cast<const float4*>(&src[(size_t)(gr * W0 + gc) * HD + c4 * 4]);
        }
        float* dst = mat ? sm.v_halo : sm.k_halo;
        *reinterpret_cast<float4*>(&dst[row * KST + c4 * 4]) = val;
    }
    {
        const float* kpsrc = g_kp + (size_t)bh * PLEN * HD;
        const float* vpsrc = g_vp + (size_t)bh * PLEN * HD;
        for (int f = tid; f < PLEN * 16; f += 256) {
            int m = f >> 4, rem = f & 15, mat = rem >> 3, c4 = rem & 7;
            const float* src = mat ? vpsrc : kpsrc;
            float4 val = *reinterpret_cast<const float4*>(&src[(size_t)m * HD + c4 * 4]);
            float* dst = mat ? sm.vp : sm.kp;
            *reinterpret_cast<float4*>(&dst[m * KST + c4 * 4]) = val;
        }
    }
    for (int i = tid; i < HD * LOCAL; i += 256) {
        int d = i / LOCAL, l = i % LOCAL;
        sm.lt[l * KST + d] = ltok[h * HD * LOCAL + i];
    }
    if (tid < LOCAL) {
        sm.rpb[tid] = rpb_local[h * LOCAL + tid];
        sm.lb[tid]  = lbias[h * LOCAL + tid];
    }
    __syncthreads();

    // hoist pooled-V column (this lane's dim) into registers
    float vpreg[PLEN];
#pragma unroll
    for (int m = 0; m < PLEN; m++) vpreg[m] = sm.vp[m * KST + lane];

    const float* qs_base = g_qs + (size_t)bh * N0 * HD;
    const float* qn_base = g_qn + (size_t)bh * N0 * HD;
    const float* pb_base = g_pb + (size_t)h * N0 * 52;

    int lr = warp & 3;
    int colbase = (warp >> 2) * 14;
    int pi = tr0 + lr;

    int grp  = lane >> 4;
    int ll   = lane & 15;
    bool lact = ll < LOCAL;
    int lidx = lact ? ll : 0;
    int ldi = lidx / 3 - 1, ldj = lidx % 3 - 1;
    int mi1 = (lane < 17) ? lane + 32 : 0;

    for (int j = 0; j < 4; j++) {
        int lc[4];
#pragma unroll
        for (int i = 0; i < 4; i++) lc[i] = colbase + j * 4 + i;
        if (j == 3) { lc[2] = lc[0]; lc[3] = lc[1]; }
        int n[4], pj[4];
#pragma unroll
        for (int i = 0; i < 4; i++) { pj[i] = tc0 + lc[i]; n[i] = pi * W0 + pj[i]; }

#pragma unroll
        for (int i = 0; i < 4; i++) {
            sm.q [warp][i][lane] = qs_base[(size_t)n[i] * HD + lane];
            sm.qn[warp][i][lane] = qn_base[(size_t)n[i] * HD + lane];
        }
        // prefetch pool biases (L2 latency hidden under score loop)
        float pb0[4], pb1[4];
#pragma unroll
        for (int i = 0; i < 4; i++) {
            const float* pbp = &pb_base[(size_t)n[i] * 52];
            pb0[i] = pbp[lane];
            pb1[i] = (lane < 17) ? pbp[32 + lane] : 0.f;
        }
        __syncwarp();

        int pxA = grp, pxB = 2 + grp;
        int hrowA = lact ? ((lr + 1 + ldi) * HC + (lc[pxA] + 1 + ldj)) : 0;
        int hrowB = lact ? ((lr + 1 + ldi) * HC + (lc[pxB] + 1 + ldj)) : 0;

        float sp0[4] = {0,0,0,0}, sp1[4] = {0,0,0,0};
        float s9A = 0.f, s9B = 0.f, tlE = 0.f, tlO = 0.f;

#pragma unroll
        for (int c = 0; c < 8; c++) {
            float4 q0 = *reinterpret_cast<const float4*>(&sm.q[warp][0][c * 4]);
            float4 q1 = *reinterpret_cast<const float4*>(&sm.q[warp][1][c * 4]);
            float4 q2 = *reinterpret_cast<const float4*>(&sm.q[warp][2][c * 4]);
            float4 q3 = *reinterpret_cast<const float4*>(&sm.q[warp][3][c * 4]);
            float4 qnE = *reinterpret_cast<const float4*>(&sm.qn[warp][grp][c * 4]);
            float4 qnO = *reinterpret_cast<const float4*>(&sm.qn[warp][2 + grp][c * 4]);
            float4 kA = *reinterpret_cast<const float4*>(&sm.kp[lane * KST + c * 4]);
            float4 kB = *reinterpret_cast<const float4*>(&sm.kp[mi1 * KST + c * 4]);
            float4 k9A = *reinterpret_cast<const float4*>(&sm.k_halo[hrowA * KST + c * 4]);
            float4 k9B = *reinterpret_cast<const float4*>(&sm.k_halo[hrowB * KST + c * 4]);
            float4 l4 = *reinterpret_cast<const float4*>(&sm.lt[lidx * KST + c * 4]);

            DOT4(sp0[0], kA, q0); DOT4(sp0[1], kA, q1);
            DOT4(sp0[2], kA, q2); DOT4(sp0[3], kA, q3);
            DOT4(sp1[0], kB, q0); DOT4(sp1[1], kB, q1);
            DOT4(sp1[2], kB, q2); DOT4(sp1[3], kB, q3);
            float4 qA = grp ? q1 : q0;
            float4 qB = grp ? q3 : q2;
            DOT4(s9A, k9A, qA);
            DOT4(s9B, k9B, qB);
            DOT4(tlE, l4, qnE);
            DOT4(tlO, l4, qnO);
        }

        bool okA = lact && (pi + ldi >= 0) && (pi + ldi < H0) &&
                   (pj[pxA] + ldj >= 0) && (pj[pxA] + ldj < W0);
        bool okB = lact && (pi + ldi >= 0) && (pi + ldi < H0) &&
                   (pj[pxB] + ldj >= 0) && (pj[pxB] + ldj < W0);
        float e9A = okA ? __expf(s9A + sm.rpb[lidx]) : 0.f;
        float e9B = okB ? __expf(s9B + sm.rpb[lidx]) : 0.f;

        float e0[4], e1[4], el[4], inv[4];
#pragma unroll
        for (int i = 0; i < 4; i++) {
            e0[i] = __expf(sp0[i] + pb0[i]);
            e1[i] = (lane < 17) ? __expf(sp1[i] + pb1[i]) : 0.f;
            el[i] = ((i & 1) == grp) ? (i < 2 ? e9A : e9B) : 0.f;
            float s = e0[i] + e1[i] + el[i];
#pragma unroll
            for (int o = 16; o; o >>= 1) s += __shfl_xor_sync(0xffffffffu, s, o);
            inv[i] = 1.f / s;
        }

#pragma unroll
        for (int i = 0; i < 4; i++) {
            sm.ap[warp][i][lane] = e0[i] * inv[i];
            if (lane < 17) sm.ap[warp][i][32 + lane] = e1[i] * inv[i];
        }
        if (lact) {
            sm.a9[warp][pxA][lidx] = e9A * inv[pxA] + tlE + sm.lb[lidx];
            sm.a9[warp][pxB][lidx] = e9B * inv[pxB] + tlO + sm.lb[lidx];
        }
        __syncwarp();

        float out[4] = {0.f, 0.f, 0.f, 0.f};
#pragma unroll
        for (int g = 0; g < 12; g++) {
            float4 a0 = *reinterpret_cast<const float4*>(&sm.ap[warp][0][g * 4]);
            float4 a1 = *reinterpret_cast<const float4*>(&sm.ap[warp][1][g * 4]);
            float4 a2 = *reinterpret_cast<const float4*>(&sm.ap[warp][2][g * 4]);
            float4 a3 = *reinterpret_cast<const float4*>(&sm.ap[warp][3][g * 4]);
            float v0 = vpreg[g * 4 + 0];
            float v1 = vpreg[g * 4 + 1];
            float v2 = vpreg[g * 4 + 2];
            float v3 = vpreg[g * 4 + 3];
            out[0] += a0.x * v0 + a0.y * v1 + a0.z * v2 + a0.w * v3;
            out[1] += a1.x * v0 + a1.y * v1 + a1.z * v2 + a1.w * v3;
            out[2] += a2.x * v0 + a2.y * v1 + a2.z * v2 + a2.w * v3;
            out[3] += a3.x * v0 + a3.y * v1 + a3.z * v2 + a3.w * v3;
        }
        {
            float v = vpreg[48];
#pragma unroll
            for (int i = 0; i < 4; i++) out[i] += sm.ap[warp][i][48] * v;
        }
        int hb[4];
#pragma unroll
        for (int i = 0; i < 4; i++) hb[i] = (lr + 1) * HC + lc[i] + 1;
#pragma unroll
        for (int l = 0; l < LOCAL; l++) {
            int roff = (l / 3 - 1) * HC + (l % 3 - 1);
#pragma unroll
            for (int i = 0; i < 4; i++) {
                out[i] += sm.a9[warp][i][l] * sm.v_halo[(hb[i] + roff) * KST + lane];
            }
        }

#pragma unroll
        for (int i = 0; i < 4; i++) {
            if (j == 3 && i >= 2) break;
            float o = out[i];
            float nb = __shfl_down_sync(0xffffffffu, o, 1);
            if ((lane & 1) == 0) {
                uint32_t hi, lo;
                split2(o, nb, hi, lo);
                size_t base = ((size_t)(b * N0 + n[i])) * 128 + h * 16 + (lane >> 1);
                g_xoH[base] = hi;
                g_xoL[base] = lo;
            }
        }
        __syncwarp();
    }
}

// ---------------- launch ----------------
extern "C" void kernel_launch(void* const* d_in, const int* in_sizes, int n_in,
                              void* d_out, int out_size)
{
    const float* x      = (const float*)d_in[0];
    const float* sls    = (const float*)d_in[1];
    const float* rct    = (const float*)d_in[2];
    const float* q_w    = (const float*)d_in[3];
    const float* q_b    = (const float*)d_in[4];
    const float* qe     = (const float*)d_in[5];
    const float* temp   = (const float*)d_in[6];
    const float* kv_w   = (const float*)d_in[7];
    const float* kv_b   = (const float*)d_in[8];
    const float* sr_w   = (const float*)d_in[9];
    const float* sr_b   = (const float*)d_in[10];
    const float* norm_g = (const float*)d_in[11];
    const float* norm_b = (const float*)d_in[12];
    const float* fc1_w  = (const float*)d_in[13];
    const float* fc1_b  = (const float*)d_in[14];
    const float* fc2_w  = (const float*)d_in[15];
    const float* fc2_b  = (const float*)d_in[16];
    const float* rpb    = (const float*)d_in[17];
    const float* lt     = (const float*)d_in[18];
    const float* lb     = (const float*)d_in[19];
    const float* proj_w = (const float*)d_in[20];
    const float* proj_b = (const float*)d_in[21];
    const int*   rpi    = (const int*)d_in[22];
    float* out = (float*)d_out;

    cudaFuncSetAttribute(gemm_mma_kernel<0>, cudaFuncAttributeMaxDynamicSharedMemorySize, GEMM_SMEM);
    cudaFuncSetAttribute(gemm_mma_kernel<1>, cudaFuncAttributeMaxDynamicSharedMemorySize, GEMM_SMEM);
    cudaFuncSetAttribute(attn_kernel, cudaFuncAttributeMaxDynamicSharedMemorySize, (int)sizeof(AttnSmem));

    // 1-3) conversions + cpb
    convert_x_kernel<<<MROWS * DIM / 4 / 256, 256>>>(x);
    convert_w_kernel<<<1280 * 128 / 256, 256>>>(q_w, kv_w, sr_w, proj_w);
    cpb_kernel<<<LTAB / 8, 256>>>(rct, fc1_w, fc1_b, fc2_w, fc2_b);

    // 4) fused GEMM1 (R12 config: 128x64 tiles, k32, 3-stage, 2 CTAs/SM)
    dim3 g1(MROWS / 128, 1024 / 64);
    gemm_mma_kernel<0><<<g1, 256, GEMM_SMEM>>>(q_b, kv_b, sr_b, qe, temp, sls, nullptr);

    // 5) pool_bias precompute
    pb_kernel<<<(HEADS * N0 * PLEN + 255) / 256, 256>>>(rpi);

    // 6) fused pool + LN + kvp
    poolkvp_kernel<<<dim3(B_ * PLEN / 4, 2), 256>>>(norm_g, norm_b, kv_w, kv_b);

    // 7) fused attention (with pb prefetch)
    attn_kernel<<<dim3(B_ * HEADS, 28), 256, sizeof(AttnSmem)>>>(rpb, lt, lb);

    // 8) proj GEMM -> d_out
    dim3 g7(MROWS / 128, 256 / 64);
    gemm_mma_kernel<1><<<g7, 256, GEMM_SMEM>>>(proj_b, nullptr, nullptr, nullptr, nullptr, nullptr, out);
}

// round 15
// speedup vs baseline: 1.1069x; 1.0508x over previous
#include <cuda_runtime.h>
#include <cuda_bf16.h>
#include <math.h>
#include <stdint.h>

// ---------------- problem constants (all static) ----------------
constexpr int B_    = 8;
constexpr int H0    = 56;
constexpr int W0    = 56;
constexpr int N0    = H0 * W0;        // 3136
constexpr int DIM   = 256;
constexpr int HEADS = 8;
constexpr int HD    = 32;
constexpr int LOCAL = 9;
constexpr int PW    = 7;
constexpr int PLEN  = 49;
constexpr int LTAB  = 4096;
constexpr int MROWS = B_ * N0;        // 25088

// ---------------- scratch (device globals; no allocs) ----------------
__device__ float g_qs[B_*HEADS*N0*HD];
__device__ float g_qn[B_*HEADS*N0*HD];
__device__ float g_k [B_*HEADS*N0*HD];
__device__ float g_v [B_*HEADS*N0*HD];
__device__ float g_xs[B_*N0*DIM];
__device__ float g_kp[B_*HEADS*PLEN*HD];
__device__ float g_vp[B_*HEADS*PLEN*HD];
__device__ float g_tab[LTAB*HEADS];
__device__ float g_pb[HEADS*N0*52];      // precomputed pool_bias [h][n][m]

// packed bf16 hi/lo operands (u32 = 2 bf16 along k)
__device__ uint32_t g_xH [MROWS*128];
__device__ uint32_t g_xL [MROWS*128];
__device__ uint32_t g_xoH[MROWS*128];
__device__ uint32_t g_xoL[MROWS*128];
__device__ uint32_t g_wH [1280*128];     // fused W [col][k2]: q|k|v|sr|proj
__device__ uint32_t g_wL [1280*128];

// ---------------- helpers ----------------
__device__ __forceinline__ uint32_t pack_bf2(__nv_bfloat16 x, __nv_bfloat16 y) {
    __nv_bfloat162 t; t.x = x; t.y = y;
    return *reinterpret_cast<uint32_t*>(&t);
}
__device__ __forceinline__ void split2(float x, float y, uint32_t& hi, uint32_t& lo) {
    __nv_bfloat16 xh = __float2bfloat16_rn(x);
    __nv_bfloat16 yh = __float2bfloat16_rn(y);
    float xr = x - __bfloat162float(xh);
    float yr = y - __bfloat162float(yh);
    hi = pack_bf2(xh, yh);
    lo = pack_bf2(__float2bfloat16_rn(xr), __float2bfloat16_rn(yr));
}

#define MMA16816(d, a0,a1,a2,a3, b0,b1) \
    asm volatile("mma.sync.aligned.m16n8k16.row.col.f32.bf16.bf16.f32 " \
        "{%0,%1,%2,%3},{%4,%5,%6,%7},{%8,%9},{%0,%1,%2,%3};" \
        : "+f"(d[0]), "+f"(d[1]), "+f"(d[2]), "+f"(d[3]) \
        : "r"(a0), "r"(a1), "r"(a2), "r"(a3), "r"(b0), "r"(b1))

#define LDSM4(r, addr) \
    asm volatile("ldmatrix.sync.aligned.m8n8.x4.shared.b16 {%0,%1,%2,%3}, [%4];" \
        : "=r"((r)[0]), "=r"((r)[1]), "=r"((r)[2]), "=r"((r)[3]) : "r"(addr))

__device__ __forceinline__ void cp16(uint32_t dst, const void* src) {
    asm volatile("cp.async.cg.shared.global [%0], [%1], 16;" :: "r"(dst), "l"(src));
}

#define DOT4(acc, a, b) (acc) += (a).x*(b).x + (a).y*(b).y + (a).z*(b).z + (a).w*(b).w

// ---------------- conversion kernels ----------------
__global__ __launch_bounds__(256)
void convert_x_kernel(const float* __restrict__ x)
{
    int i = blockIdx.x * 256 + threadIdx.x;
    float4 v = reinterpret_cast<const float4*>(x)[i];
    uint32_t h0, l0, h1, l1;
    split2(v.x, v.y, h0, l0);
    split2(v.z, v.w, h1, l1);
    g_xH[i * 2] = h0; g_xH[i * 2 + 1] = h1;
    g_xL[i * 2] = l0; g_xL[i * 2 + 1] = l1;
}

__global__ __launch_bounds__(256)
void convert_w_kernel(const float* __restrict__ q_w, const float* __restrict__ kv_w,
                      const float* __restrict__ sr_w, const float* __restrict__ proj_w)
{
    int idx = blockIdx.x * 256 + threadIdx.x;        // 1280*128
    int c = idx >> 7, k2 = idx & 127;
    float f0, f1;
    if (c < 256)       { f0 = q_w [(2*k2)   * 256 + c];        f1 = q_w [(2*k2+1) * 256 + c];        }
    else if (c < 768)  { f0 = kv_w[(2*k2)   * 512 + c - 256];  f1 = kv_w[(2*k2+1) * 512 + c - 256];  }
    else if (c < 1024) { f0 = sr_w[(2*k2)   * 256 + c - 768];  f1 = sr_w[(2*k2+1) * 256 + c - 768];  }
    else               { f0 = proj_w[(2*k2) * 256 + c - 1024]; f1 = proj_w[(2*k2+1) * 256 + c - 1024]; }
    uint32_t h, l;
    split2(f0, f1, h, l);
    g_wH[idx] = h; g_wL[idx] = l;
}

__global__ void cpb_kernel(const float* __restrict__ rct,
                           const float* __restrict__ w1, const float* __restrict__ b1,
                           const float* __restrict__ w2, const float* __restrict__ b2)
{
    int gw = (blockIdx.x * blockDim.x + threadIdx.x) >> 5;
    int lane = threadIdx.x & 31;
    if (gw >= LTAB) return;
    float r0 = rct[gw * 2], r1 = rct[gw * 2 + 1];
    float acc[HEADS];
#pragma unroll
    for (int h = 0; h < HEADS; h++) acc[h] = 0.f;
    for (int j = lane; j < 512; j += 32) {
        float hv = fmaxf(r0 * w1[j] + r1 * w1[512 + j] + b1[j], 0.f);
#pragma unroll
        for (int h = 0; h < HEADS; h++) acc[h] += hv * w2[j * HEADS + h];
    }
#pragma unroll
    for (int h = 0; h < HEADS; h++)
#pragma unroll
        for (int o = 16; o; o >>= 1) acc[h] += __shfl_xor_sync(0xffffffffu, acc[h], o);
    if (lane == 0) {
#pragma unroll
        for (int h = 0; h < HEADS; h++) g_tab[gw * HEADS + h] = acc[h] + b2[h];
    }
}

__global__ __launch_bounds__(256)
void pb_kernel(const int* __restrict__ rpi)
{
    int idx = blockIdx.x * 256 + threadIdx.x;
    if (idx >= HEADS * N0 * PLEN) return;
    int m = idx % PLEN;
    int hn = idx / PLEN;
    int h = hn / N0, n = hn % N0;
    g_pb[(size_t)hn * 52 + m] = g_tab[rpi[n * PLEN + m] * HEADS + h];
}

// ---------------- bf16x3 tensor-core GEMM, 128x64 tile, 3-stage pipeline (R12) ----------------
constexpr int LDU = 20;
constexpr uint32_t SM_AL = 10240;
constexpr uint32_t SM_BH = 20480;
constexpr uint32_t SM_BL = 25600;
constexpr uint32_t SM_STAGE = 30720;
constexpr int GEMM_SMEM = 92160;         // 3 stages

template<int MODE>
__global__ __launch_bounds__(256, 2)
void gemm_mma_kernel(const float* __restrict__ bq, const float* __restrict__ bkv,
                     const float* __restrict__ bsr,
                     const float* __restrict__ qe, const float* __restrict__ temp,
                     const float* __restrict__ sls,
                     float* __restrict__ Out)
{
    extern __shared__ uint32_t sm_u[];
    uint32_t sbase = (uint32_t)__cvta_generic_to_shared(sm_u);

    const uint32_t* AH = MODE ? g_xoH : g_xH;
    const uint32_t* AL = MODE ? g_xoL : g_xL;

    int tid  = threadIdx.x;
    int lane = tid & 31;
    int warp = tid >> 5;
    int wm   = warp >> 1;
    int wn   = warp & 1;

    int m0    = blockIdx.x * 128;
    int col0  = blockIdx.y * 64;
    int bcol0 = col0 + (MODE ? 1024 : 0);

    int lrowA = tid >> 1;
    int loffA = (tid & 1) * 8;
    uint32_t dstA = (uint32_t)(lrowA * LDU + loffA) * 4;
    int lrowB = tid >> 2;
    int loffB = (tid & 3) * 4;
    uint32_t dstB = (uint32_t)(lrowB * LDU + loffB) * 4;

    const uint32_t* aHp = &AH  [(size_t)(m0 + lrowA)    * 128 + loffA];
    const uint32_t* aLp = &AL  [(size_t)(m0 + lrowA)    * 128 + loffA];
    const uint32_t* bHp = &g_wH[(size_t)(bcol0 + lrowB) * 128 + loffB];
    const uint32_t* bLp = &g_wL[(size_t)(bcol0 + lrowB) * 128 + loffB];

    int aRow  = wm * 32 + (lane & 7) + ((lane >> 3) & 1) * 8;
    int aCol4 = ((lane >> 4) & 1) * 4;
    uint32_t aoff[2][2];
#pragma unroll
    for (int mt = 0; mt < 2; mt++)
#pragma unroll
        for (int s = 0; s < 2; s++)
            aoff[mt][s] = (uint32_t)(((aRow + mt * 16) * LDU) + s * 8 + aCol4) * 4;
    int bRow  = wn * 32 + (lane & 7);
    int bCol4 = ((lane >> 3) & 3) * 4;
    uint32_t boff[4];
#pragma unroll
    for (int nt = 0; nt < 4; nt++)
        boff[nt] = (uint32_t)(((bRow + nt * 8) * LDU) + bCol4) * 4;

    float acc[2][4][4];
#pragma unroll
    for (int i = 0; i < 2; i++)
#pragma unroll
        for (int j = 0; j < 4; j++)
#pragma unroll
            for (int e = 0; e < 4; e++) acc[i][j][e] = 0.f;

#define ISSUE_STAGE(it, buf) do { \
    uint32_t st_ = sbase + (uint32_t)(buf) * SM_STAGE; \
    cp16(st_ + dstA,              aHp + (it) * 16); \
    cp16(st_ + dstA + 16,         aHp + (it) * 16 + 4); \
    cp16(st_ + SM_AL + dstA,      aLp + (it) * 16); \
    cp16(st_ + SM_AL + dstA + 16, aLp + (it) * 16 + 4); \
    cp16(st_ + SM_BH + dstB,      bHp + (it) * 16); \
    cp16(st_ + SM_BL + dstB,      bLp + (it) * 16); \
    asm volatile("cp.async.commit_group;"); \
} while (0)

    ISSUE_STAGE(0, 0);
    ISSUE_STAGE(1, 1);

#pragma unroll
    for (int it = 0; it < 8; it++) {
        if (it < 7) {
            asm volatile("cp.async.wait_group 1;");
        } else {
            asm volatile("cp.async.wait_group 0;");
        }
        __syncthreads();
        {
            uint32_t st = sbase + (uint32_t)(it % 3) * SM_STAGE;
            uint32_t bHf[4][4], bLf[4][4];
#pragma unroll
            for (int nt = 0; nt < 4; nt++) {
                LDSM4(bHf[nt], st + SM_BH + boff[nt]);
                LDSM4(bLf[nt], st + SM_BL + boff[nt]);
            }
#pragma unroll
            for (int s = 0; s < 2; s++) {
                uint32_t aHf[2][4], aLf[2][4];
#pragma unroll
                for (int mt = 0; mt < 2; mt++) {
                    LDSM4(aHf[mt], st + aoff[mt][s]);
                    LDSM4(aLf[mt], st + SM_AL + aoff[mt][s]);
                }
#pragma unroll
                for (int mt = 0; mt < 2; mt++)
#pragma unroll
                    for (int nt = 0; nt < 4; nt++) {
                        MMA16816(acc[mt][nt], aHf[mt][0], aHf[mt][1], aHf[mt][2], aHf[mt][3],
                                 bHf[nt][2*s], bHf[nt][2*s+1]);
                        MMA16816(acc[mt][nt], aHf[mt][0], aHf[mt][1], aHf[mt][2], aHf[mt][3],
                                 bLf[nt][2*s], bLf[nt][2*s+1]);
                        MMA16816(acc[mt][nt], aLf[mt][0], aLf[mt][1], aLf[mt][2], aLf[mt][3],
                                 bHf[nt][2*s], bHf[nt][2*s+1]);
                    }
            }
        }
        if (it < 6) ISSUE_STAGE(it + 2, (it + 2) % 3);
    }
#undef ISSUE_STAGE

    // ---------------- epilogue ----------------
    if (MODE == 1) {
#pragma unroll
        for (int mt = 0; mt < 2; mt++) {
            int r0 = m0 + wm * 32 + mt * 16 + (lane >> 2);
#pragma unroll
            for (int nt = 0; nt < 4; nt++) {
                int c0 = col0 + wn * 32 + nt * 8 + (lane & 3) * 2;
                Out[(size_t)r0 * DIM + c0]           = acc[mt][nt][0] + bq[c0];
                Out[(size_t)r0 * DIM + c0 + 1]       = acc[mt][nt][1] + bq[c0 + 1];
                Out[(size_t)(r0 + 8) * DIM + c0]     = acc[mt][nt][2] + bq[c0];
                Out[(size_t)(r0 + 8) * DIM + c0 + 1] = acc[mt][nt][3] + bq[c0 + 1];
            }
        }
        return;
    }

    int strip = (col0 + wn * 32) >> 5;
#pragma unroll
    for (int mt = 0; mt < 2; mt++)
#pragma unroll
        for (int nt = 0; nt < 4; nt++) {
            int c = col0 + wn * 32 + nt * 8 + (lane & 3) * 2;
            float b0, b1;
            if (c < 256)      { b0 = bq[c];        b1 = bq[c + 1];    }
            else if (c < 768) { b0 = bkv[c - 256]; b1 = bkv[c - 255]; }
            else              { b0 = bsr[c - 768]; b1 = bsr[c - 767]; }
            acc[mt][nt][0] += b0; acc[mt][nt][1] += b1;
            acc[mt][nt][2] += b0; acc[mt][nt][3] += b1;
        }

    if (strip < 16) {
        int h = strip & 7;
        bool isq = strip < 8;
        float spsls = 0.f;
        if (isq) spsls = log1pf(expf(temp[h])) * sls[0];
#pragma unroll
        for (int mt = 0; mt < 2; mt++) {
            float ss0 = 0.f, ss1 = 0.f;
#pragma unroll
            for (int nt = 0; nt < 4; nt++) {
                ss0 += acc[mt][nt][0] * acc[mt][nt][0] + acc[mt][nt][1] * acc[mt][nt][1];
                ss1 += acc[mt][nt][2] * acc[mt][nt][2] + acc[mt][nt][3] * acc[mt][nt][3];
            }
            ss0 += __shfl_xor_sync(0xffffffffu, ss0, 1);
            ss0 += __shfl_xor_sync(0xffffffffu, ss0, 2);
            ss1 += __shfl_xor_sync(0xffffffffu, ss1, 1);
            ss1 += __shfl_xor_sync(0xffffffffu, ss1, 2);
            float inv0 = 1.f / fmaxf(sqrtf(ss0), 1e-12f);
            float inv1 = 1.f / fmaxf(sqrtf(ss1), 1e-12f);
            int r0 = m0 + wm * 32 + mt * 16 + (lane >> 2);
            int b0i = r0 / N0, n0i = r0 % N0;
            int b1i = (r0 + 8) / N0, n1i = (r0 + 8) % N0;
            size_t base0 = (((size_t)(b0i * HEADS + h)) * N0 + n0i) * HD;
            size_t base1 = (((size_t)(b1i * HEADS + h)) * N0 + n1i) * HD;
#pragma unroll
            for (int nt = 0; nt < 4; nt++) {
                int d0 = (wn * 32 + nt * 8 + (lane & 3) * 2) & 31;
#pragma unroll
                for (int p = 0; p < 2; p++) {
                    int d = d0 + p;
                    float v0 = acc[mt][nt][p]     * inv0;
                    float v1 = acc[mt][nt][2 + p] * inv1;
                    if (isq) {
                        float e = qe[h * HD + d];
                        g_qn[base0 + d] = v0;
                        g_qn[base1 + d] = v1;
                        g_qs[base0 + d] = (v0 + e) * spsls;
                        g_qs[base1 + d] = (v1 + e) * spsls;
                    } else {
                        g_k[base0 + d] = v0;
                        g_k[base1 + d] = v1;
                    }
                }
            }
        }
    } else if (strip < 24) {
        int h = strip & 7;
#pragma unroll
        for (int mt = 0; mt < 2; mt++) {
            int r0 = m0 + wm * 32 + mt * 16 + (lane >> 2);
            int ba = r0 / N0, na = r0 % N0;
            int bb = (r0 + 8) / N0, nb = (r0 + 8) % N0;
            size_t base0 = (((size_t)(ba * HEADS + h)) * N0 + na) * HD;
            size_t base1 = (((size_t)(bb * HEADS + h)) * N0 + nb) * HD;
#pragma unroll
            for (int nt = 0; nt < 4; nt++) {
                int d = (wn * 32 + nt * 8 + (lane & 3) * 2) & 31;
                g_v[base0 + d]     = acc[mt][nt][0];
                g_v[base0 + d + 1] = acc[mt][nt][1];
                g_v[base1 + d]     = acc[mt][nt][2];
                g_v[base1 + d + 1] = acc[mt][nt][3];
            }
        }
    } else {
#pragma unroll
        for (int mt = 0; mt < 2; mt++) {
            int r0 = m0 + wm * 32 + mt * 16 + (lane >> 2);
            int ba = r0 / N0, na = r0 % N0;
            int bb = (r0 + 8) / N0, nb = (r0 + 8) % N0;
#pragma unroll
            for (int nt = 0; nt < 4; nt++) {
                int cc = (wn * 32 + nt * 8 + (lane & 3) * 2) + col0 - 768;
#pragma unroll
                for (int p = 0; p < 2; p++) {
                    float v0 = acc[mt][nt][p];
                    float v1 = acc[mt][nt][2 + p];
                    g_xs[((size_t)(ba * N0 + na)) * DIM + cc + p] =
                        0.5f * v0 * (1.f + erff(v0 * 0.70710678118654752f));
                    g_xs[((size_t)(bb * N0 + nb)) * DIM + cc + p] =
                        0.5f * v1 * (1.f + erff(v1 * 0.70710678118654752f));
                }
            }
        }
    }
}

// ---------------- fused pool + LN + kvp ----------------
__global__ __launch_bounds__(256)
void poolkvp_kernel(const float* __restrict__ gamma, const float* __restrict__ beta,
                    const float* __restrict__ kv_w, const float* __restrict__ kv_b)
{
    __shared__ float xr[4][DIM];
    __shared__ float redm[4][8], redv[4][8];
    int bp0 = blockIdx.x * 4;
    int half = blockIdx.y;
    int tid = threadIdx.x, lane = tid & 31, wp = tid >> 5;

    float sv[4];
#pragma unroll
    for (int i = 0; i < 4; i++) {
        int bp = bp0 + i, b = bp / PLEN, p = bp % PLEN;
        int pi = p / PW, pj = p % PW;
        float s = 0.f;
#pragma unroll
        for (int r = 0; r < 8; r++)
#pragma unroll
            for (int c = 0; c < 8; c++)
                s += g_xs[((size_t)(b * N0 + (pi * 8 + r) * W0 + pj * 8 + c)) * DIM + tid];
        sv[i] = s * (1.f / 64.f);
    }
#pragma unroll
    for (int i = 0; i < 4; i++) {
        float m = sv[i];
#pragma unroll
        for (int o = 16; o; o >>= 1) m += __shfl_xor_sync(0xffffffffu, m, o);
        if (lane == 0) redm[i][wp] = m;
    }
    __syncthreads();
    float dv[4];
#pragma unroll
    for (int i = 0; i < 4; i++) {
        float mean = 0.f;
#pragma unroll
        for (int w = 0; w < 8; w++) mean += redm[i][w];
        mean *= (1.f / 256.f);
        dv[i] = sv[i] - mean;
        float v2 = dv[i] * dv[i];
#pragma unroll
        for (int o = 16; o; o >>= 1) v2 += __shfl_xor_sync(0xffffffffu, v2, o);
        if (lane == 0) redv[i][wp] = v2;
    }
    __syncthreads();
#pragma unroll
    for (int i = 0; i < 4; i++) {
        float var = 0.f;
#pragma unroll
        for (int w = 0; w < 8; w++) var += redv[i][w];
        var *= (1.f / 256.f);
        xr[i][tid] = dv[i] * rsqrtf(var + 1e-5f) * gamma[tid] + beta[tid];
    }
    __syncthreads();

    int yoff = half * 256;
    float bb = kv_b[yoff + tid];
    float acc[4];
#pragma unroll
    for (int i = 0; i < 4; i++) acc[i] = bb;

#pragma unroll 8
    for (int kk = 0; kk < DIM; kk++) {
        float w = kv_w[(size_t)kk * 512 + yoff + tid];
#pragma unroll
        for (int i = 0; i < 4; i++) acc[i] = fmaf(xr[i][kk], w, acc[i]);
    }

#pragma unroll
    for (int i = 0; i < 4; i++) {
        int bp = bp0 + i;
        int b = bp / PLEN, p = bp % PLEN;
        size_t dst = (((size_t)(b * HEADS + wp)) * PLEN + p) * HD + lane;
        if (half == 0) {
            float ss = acc[i] * acc[i];
#pragma unroll
            for (int o = 16; o; o >>= 1) ss += __shfl_xor_sync(0xffffffffu, ss, o);
            g_kp[dst] = acc[i] / fmaxf(sqrtf(ss), 1e-12f);
        } else {
            g_vp[dst] = acc[i];
        }
    }
}

// ---------------- fused attention: quad-pixel, tiled halo, no-max softmax ----------------
// j-loop fully unrolled; j==3 pass does only 2 real pixels (dead slots eliminated)
constexpr int TR = 4, TC = 28, HR = 6, HC = 30;
constexpr int KST = 36;
constexpr int QST = 36;

struct AttnSmem {
    float k_halo[HR * HC * KST];
    float v_halo[HR * HC * KST];
    float kp[PLEN * KST];
    float vp[PLEN * KST];
    float lt[LOCAL * KST];
    float q  [8][4][QST];
    float qn [8][4][QST];
    float a9 [8][4][12];
    float ap [8][4][52];
    float rpb[LOCAL];
    float lb [LOCAL];
};

__global__ __launch_bounds__(256, 2)
void attn_kernel(const float* __restrict__ rpb_local,
                 const float* __restrict__ ltok,
                 const float* __restrict__ lbias)
{
    extern __shared__ char smem_raw[];
    AttnSmem& sm = *reinterpret_cast<AttnSmem*>(smem_raw);

    int bh = blockIdx.x;
    int b = bh / HEADS, h = bh % HEADS;
    int ty = blockIdx.y;
    int tr0 = (ty % 14) * TR;
    int tc0 = (ty / 14) * TC;
    int tid = threadIdx.x, warp = tid >> 5, lane = tid & 31;

    const float* k_base = g_k + (size_t)bh * N0 * HD;
    const float* v_base = g_v + (size_t)bh * N0 * HD;

    for (int f = tid; f < HR * HC * 16; f += 256) {
        int row = f >> 4;
        int rem = f & 15;
        int mat = rem >> 3;
        int c4  = rem & 7;
        int hr = row / HC, hc = row % HC;
        int gr = tr0 - 1 + hr, gc = tc0 - 1 + hc;
        bool ok = (gr >= 0 && gr < H0 && gc >= 0 && gc < W0);
        float4 val = make_float4(0.f, 0.f, 0.f, 0.f);
        if (ok) {
            const float* src = mat ? v_base : k_base;
            val = *reinterpret_cast<const float4*>(&src[(size_t)(gr * W0 + gc) * HD + c4 * 4]);
        }
        float* dst = mat ? sm.v_halo : sm.k_halo;
        *reinterpret_cast<float4*>(&dst[row * KST + c4 * 4]) = val;
    }
    {
        const float* kpsrc = g_kp + (size_t)bh * PLEN * HD;
        const float* vpsrc = g_vp + (size_t)bh * PLEN * HD;
        for (int f = tid; f < PLEN * 16; f += 256) {
            int m = f >> 4, rem = f & 15, mat = rem >> 3, c4 = rem & 7;
            const float* src = mat ? vpsrc : kpsrc;
            float4 val = *reinterpret_cast<const float4*>(&src[(size_t)m * HD + c4 * 4]);
            float* dst = mat ? sm.vp : sm.kp;
            *reinterpret_cast<float4*>(&dst[m * KST + c4 * 4]) = val;
        }
    }
    for (int i = tid; i < HD * LOCAL; i += 256) {
        int d = i / LOCAL, l = i % LOCAL;
        sm.lt[l * KST + d] = ltok[h * HD * LOCAL + i];
    }
    if (tid < LOCAL) {
        sm.rpb[tid] = rpb_local[h * LOCAL + tid];
        sm.lb[tid]  = lbias[h * LOCAL + tid];
    }
    __syncthreads();

    // hoist pooled-V column (this lane's dim) into registers
    float vpreg[PLEN];
#pragma unroll
    for (int m = 0; m < PLEN; m++) vpreg[m] = sm.vp[m * KST + lane];

    const float* qs_base = g_qs + (size_t)bh * N0 * HD;
    const float* qn_base = g_qn + (size_t)bh * N0 * HD;
    const float* pb_base = g_pb + (size_t)h * N0 * 52;

    int lr = warp & 3;
    int colbase = (warp >> 2) * 14;
    int pi = tr0 + lr;

    int grp  = lane >> 4;
    int ll   = lane & 15;
    bool lact = ll < LOCAL;
    int lidx = lact ? ll : 0;
    int ldi = lidx / 3 - 1, ldj = lidx % 3 - 1;
    int mi1 = (lane < 17) ? lane + 32 : 0;

#pragma unroll
    for (int j = 0; j < 4; j++) {
        const bool full = (j < 3);             // compile-time after unroll
        int lc[4];
#pragma unroll
        for (int i = 0; i < 4; i++) lc[i] = colbase + j * 4 + i;
        if (j == 3) { lc[2] = lc[0]; lc[3] = lc[1]; }
        int n[4], pj[4];
#pragma unroll
        for (int i = 0; i < 4; i++) { pj[i] = tc0 + lc[i]; n[i] = pi * W0 + pj[i]; }

#pragma unroll
        for (int i = 0; i < 4; i++) {
            if (!full && i >= 2) break;
            sm.q [warp][i][lane] = qs_base[(size_t)n[i] * HD + lane];
            sm.qn[warp][i][lane] = qn_base[(size_t)n[i] * HD + lane];
        }
        __syncwarp();

        int pxA = grp, pxB = 2 + grp;
        int hrowA = lact ? ((lr + 1 + ldi) * HC + (lc[pxA] + 1 + ldj)) : 0;
        int hrowB = (full && lact) ? ((lr + 1 + ldi) * HC + (lc[pxB] + 1 + ldj)) : 0;

        float sp0[4] = {0,0,0,0}, sp1[4] = {0,0,0,0};
        float s9A = 0.f, s9B = 0.f, tlE = 0.f, tlO = 0.f;

#pragma unroll
        for (int c = 0; c < 8; c++) {
            float4 q0 = *reinterpret_cast<const float4*>(&sm.q[warp][0][c * 4]);
            float4 q1 = *reinterpret_cast<const float4*>(&sm.q[warp][1][c * 4]);
            float4 qnE = *reinterpret_cast<const float4*>(&sm.qn[warp][grp][c * 4]);
            float4 kA = *reinterpret_cast<const float4*>(&sm.kp[lane * KST + c * 4]);
            float4 kB = *reinterpret_cast<const float4*>(&sm.kp[mi1 * KST + c * 4]);
            float4 k9A = *reinterpret_cast<const float4*>(&sm.k_halo[hrowA * KST + c * 4]);
            float4 l4 = *reinterpret_cast<const float4*>(&sm.lt[lidx * KST + c * 4]);

            DOT4(sp0[0], kA, q0); DOT4(sp0[1], kA, q1);
            DOT4(sp1[0], kB, q0); DOT4(sp1[1], kB, q1);
            float4 qA = grp ? q1 : q0;
            DOT4(s9A, k9A, qA);
            DOT4(tlE, l4, qnE);

            if (full) {
                float4 q2 = *reinterpret_cast<const float4*>(&sm.q[warp][2][c * 4]);
                float4 q3 = *reinterpret_cast<const float4*>(&sm.q[warp][3][c * 4]);
                float4 qnO = *reinterpret_cast<const float4*>(&sm.qn[warp][2 + grp][c * 4]);
                float4 k9B = *reinterpret_cast<const float4*>(&sm.k_halo[hrowB * KST + c * 4]);
                DOT4(sp0[2], kA, q2); DOT4(sp0[3], kA, q3);
                DOT4(sp1[2], kB, q2); DOT4(sp1[3], kB, q3);
                float4 qB = grp ? q3 : q2;
                DOT4(s9B, k9B, qB);
                DOT4(tlO, l4, qnO);
            }
        }

        float pb0[4], pb1[4];
#pragma unroll
        for (int i = 0; i < 4; i++) {
            if (!full && i >= 2) break;
            const float* pbp = &pb_base[(size_t)n[i] * 52];
            pb0[i] = pbp[lane];
            pb1[i] = (lane < 17) ? pbp[32 + lane] : 0.f;
        }

        bool okA = lact && (pi + ldi >= 0) && (pi + ldi < H0) &&
                   (pj[pxA] + ldj >= 0) && (pj[pxA] + ldj < W0);
        float e9A = okA ? __expf(s9A + sm.rpb[lidx]) : 0.f;
        float e9B = 0.f;
        if (full) {
            bool okB = lact && (pi + ldi >= 0) && (pi + ldi < H0) &&
                       (pj[pxB] + ldj >= 0) && (pj[pxB] + ldj < W0);
            e9B = okB ? __expf(s9B + sm.rpb[lidx]) : 0.f;
        }

        float e0[4], e1[4], el[4], inv[4];
#pragma unroll
        for (int i = 0; i < 4; i++) {
            if (!full && i >= 2) break;
            e0[i] = __expf(sp0[i] + pb0[i]);
            e1[i] = (lane < 17) ? __expf(sp1[i] + pb1[i]) : 0.f;
            el[i] = ((i & 1) == grp) ? (i < 2 ? e9A : e9B) : 0.f;
            float s = e0[i] + e1[i] + el[i];
#pragma unroll
            for (int o = 16; o; o >>= 1) s += __shfl_xor_sync(0xffffffffu, s, o);
            inv[i] = 1.f / s;
        }

#pragma unroll
        for (int i = 0; i < 4; i++) {
            if (!full && i >= 2) break;
            sm.ap[warp][i][lane] = e0[i] * inv[i];
            if (lane < 17) sm.ap[warp][i][32 + lane] = e1[i] * inv[i];
        }
        if (lact) {
            sm.a9[warp][pxA][lidx] = e9A * inv[pxA] + tlE + sm.lb[lidx];
            if (full)
                sm.a9[warp][pxB][lidx] = e9B * inv[pxB] + tlO + sm.lb[lidx];
        }
        __syncwarp();

        float out[4] = {0.f, 0.f, 0.f, 0.f};
#pragma unroll
        for (int g = 0; g < 12; g++) {
            float4 a0 = *reinterpret_cast<const float4*>(&sm.ap[warp][0][g * 4]);
            float4 a1 = *reinterpret_cast<const float4*>(&sm.ap[warp][1][g * 4]);
            float v0 = vpreg[g * 4 + 0];
            float v1 = vpreg[g * 4 + 1];
            float v2 = vpreg[g * 4 + 2];
            float v3 = vpreg[g * 4 + 3];
            out[0] += a0.x * v0 + a0.y * v1 + a0.z * v2 + a0.w * v3;
            out[1] += a1.x * v0 + a1.y * v1 + a1.z * v2 + a1.w * v3;
            if (full) {
                float4 a2 = *reinterpret_cast<const float4*>(&sm.ap[warp][2][g * 4]);
                float4 a3 = *reinterpret_cast<const float4*>(&sm.ap[warp][3][g * 4]);
                out[2] += a2.x * v0 + a2.y * v1 + a2.z * v2 + a2.w * v3;
                out[3] += a3.x * v0 + a3.y * v1 + a3.z * v2 + a3.w * v3;
            }
        }
        {
            float v = vpreg[48];
            out[0] += sm.ap[warp][0][48] * v;
            out[1] += sm.ap[warp][1][48] * v;
            if (full) {
                out[2] += sm.ap[warp][2][48] * v;
                out[3] += sm.ap[warp][3][48] * v;
            }
        }
        int hb[4];
#pragma unroll
        for (int i = 0; i < 4; i++) hb[i] = (lr + 1) * HC + lc[i] + 1;
#pragma unroll
        for (int l = 0; l < LOCAL; l++) {
            int roff = (l / 3 - 1) * HC + (l % 3 - 1);
            out[0] += sm.a9[warp][0][l] * sm.v_halo[(hb[0] + roff) * KST + lane];
            out[1] += sm.a9[warp][1][l] * sm.v_halo[(hb[1] + roff) * KST + lane];
            if (full) {
                out[2] += sm.a9[warp][2][l] * sm.v_halo[(hb[2] + roff) * KST + lane];
                out[3] += sm.a9[warp][3][l] * sm.v_halo[(hb[3] + roff) * KST + lane];
            }
        }

#pragma unroll
        for (int i = 0; i < 4; i++) {
            if (!full && i >= 2) break;
            float o = out[i];
            float nb = __shfl_down_sync(0xffffffffu, o, 1);
            if ((lane & 1) == 0) {
                uint32_t hi, lo;
                split2(o, nb, hi, lo);
                size_t base = ((size_t)(b * N0 + n[i])) * 128 + h * 16 + (lane >> 1);
                g_xoH[base] = hi;
                g_xoL[base] = lo;
            }
        }
        __syncwarp();
    }
}

// ---------------- launch ----------------
extern "C" void kernel_launch(void* const* d_in, const int* in_sizes, int n_in,
                              void* d_out, int out_size)
{
    const float* x      = (const float*)d_in[0];
    const float* sls    = (const float*)d_in[1];
    const float* rct    = (const float*)d_in[2];
    const float* q_w    = (const float*)d_in[3];
    const float* q_b    = (const float*)d_in[4];
    const float* qe     = (const float*)d_in[5];
    const float* temp   = (const float*)d_in[6];
    const float* kv_w   = (const float*)d_in[7];
    const float* kv_b   = (const float*)d_in[8];
    const float* sr_w   = (const float*)d_in[9];
    const float* sr_b   = (const float*)d_in[10];
    const float* norm_g = (const float*)d_in[11];
    const float* norm_b = (const float*)d_in[12];
    const float* fc1_w  = (const float*)d_in[13];
    const float* fc1_b  = (const float*)d_in[14];
    const float* fc2_w  = (const float*)d_in[15];
    const float* fc2_b  = (const float*)d_in[16];
    const float* rpb    = (const float*)d_in[17];
    const float* lt     = (const float*)d_in[18];
    const float* lb     = (const float*)d_in[19];
    const float* proj_w = (const float*)d_in[20];
    const float* proj_b = (const float*)d_in[21];
    const int*   rpi    = (const int*)d_in[22];
    float* out = (float*)d_out;

    cudaFuncSetAttribute(gemm_mma_kernel<0>, cudaFuncAttributeMaxDynamicSharedMemorySize, GEMM_SMEM);
    cudaFuncSetAttribute(gemm_mma_kernel<1>, cudaFuncAttributeMaxDynamicSharedMemorySize, GEMM_SMEM);
    cudaFuncSetAttribute(attn_kernel, cudaFuncAttributeMaxDynamicSharedMemorySize, (int)sizeof(AttnSmem));

    // 1-3) conversions + cpb
    convert_x_kernel<<<MROWS * DIM / 4 / 256, 256>>>(x);
    convert_w_kernel<<<1280 * 128 / 256, 256>>>(q_w, kv_w, sr_w, proj_w);
    cpb_kernel<<<LTAB / 8, 256>>>(rct, fc1_w, fc1_b, fc2_w, fc2_b);

    // 4) fused GEMM1 (R12 config: 128x64 tiles, k32, 3-stage, 2 CTAs/SM)
    dim3 g1(MROWS / 128, 1024 / 64);
    gemm_mma_kernel<0><<<g1, 256, GEMM_SMEM>>>(q_b, kv_b, sr_b, qe, temp, sls, nullptr);

    // 5) pool_bias precompute
    pb_kernel<<<(HEADS * N0 * PLEN + 255) / 256, 256>>>(rpi);

    // 6) fused pool + LN + kvp
    poolkvp_kernel<<<dim3(B_ * PLEN / 4, 2), 256>>>(norm_g, norm_b, kv_w, kv_b);

    // 7) fused attention (unrolled j, dead-slot elimination in final pass)
    attn_kernel<<<dim3(B_ * HEADS, 28), 256, sizeof(AttnSmem)>>>(rpb, lt, lb);

    // 8) proj GEMM -> d_out
    dim3 g7(MROWS / 128, 256 / 64);
    gemm_mma_kernel<1><<<g7, 256, GEMM_SMEM>>>(proj_b, nullptr, nullptr, nullptr, nullptr, nullptr, out);
}